// round 8
// baseline (speedup 1.0000x reference)
#include <cuda_runtime.h>
#include <cuda_fp16.h>
#include <cstdint>
#include <cstddef>

// ---------------- problem constants ----------------
#define NNODES   100000
#define DFEAT    256
#define MAXDEG   128
#define BATCH    1024
#define FAN1     25
#define FAN2     10
#define OUTD     128           // per-branch output
#define M1       (BATCH*FAN1)          // 25600
#define M2       (BATCH*FAN1*FAN2)     // 256000
#define WSZH     (OUTD * DFEAT / 2)    // half2 words per weight matrix = 16384

// ---------------- scratch (device globals; no allocation APIs) ----------------
__device__ int      d_cols1[FAN1];
__device__ int      d_cols2[FAN2];
__device__ int      d_ids1[M1];
__device__ int      d_ids2[M2];
__device__ float    d_z1[M1 * DFEAT];     // layer-1 output for ids1 rows
__device__ float    d_z0[BATCH * DFEAT];  // layer-1 output for ids rows
__device__ uint32_t d_Whh[4 * WSZH];      // fp16 hi of weights, [n][k] half2-packed
__device__ uint32_t d_Wll[4 * WSZH];      // fp16 lo

// ---------------- threefry2x32 (JAX-exact, 20 rounds) ----------------
__device__ __forceinline__ uint32_t rotl32(uint32_t v, int r) {
    return (v << r) | (v >> (32 - r));
}

__device__ __forceinline__ void tf2x32(uint32_t k0, uint32_t k1,
                                       uint32_t x0, uint32_t x1,
                                       uint32_t& y0, uint32_t& y1) {
    uint32_t ks0 = k0, ks1 = k1, ks2 = k0 ^ k1 ^ 0x1BD11BDAu;
    x0 += ks0; x1 += ks1;
    const int r0[4] = {13, 15, 26, 6};
    const int r1[4] = {17, 29, 16, 24};
#define TF_G(RR) { x0 += x1; x1 = rotl32(x1, RR[0]); x1 ^= x0; \
                   x0 += x1; x1 = rotl32(x1, RR[1]); x1 ^= x0; \
                   x0 += x1; x1 = rotl32(x1, RR[2]); x1 ^= x0; \
                   x0 += x1; x1 = rotl32(x1, RR[3]); x1 ^= x0; }
    TF_G(r0); x0 += ks1; x1 += ks2 + 1u;
    TF_G(r1); x0 += ks2; x1 += ks0 + 2u;
    TF_G(r0); x0 += ks0; x1 += ks1 + 3u;
    TF_G(r1); x0 += ks1; x1 += ks2 + 4u;
    TF_G(r0); x0 += ks2; x1 += ks0 + 5u;
#undef TF_G
    y0 = x0; y1 = x1;
}

// jax.random.permutation(k, 128) for k1,k2 = split(key(42)),
// partitionable semantics; random_bits(32) = bits1 ^ bits2 (VERIFIED round 4)
__global__ void setup_perm_kernel() {
    int t = threadIdx.x;  // 128 threads
    uint32_t k1a, k1b, k2a, k2b;
    tf2x32(0u, 42u, 0u, 0u, k1a, k1b);
    tf2x32(0u, 42u, 0u, 1u, k2a, k2b);
    uint32_t s1a, s1b, s2a, s2b;
    tf2x32(k1a, k1b, 0u, 1u, s1a, s1b);
    tf2x32(k2a, k2b, 0u, 1u, s2a, s2b);

    __shared__ uint32_t keys[MAXDEG];
    uint32_t b1, b2;

    tf2x32(s1a, s1b, 0u, (uint32_t)t, b1, b2);
    keys[t] = b1 ^ b2;
    __syncthreads();
    {
        uint32_t me = keys[t];
        int rank = 0;
        #pragma unroll 8
        for (int j = 0; j < MAXDEG; j++) {
            uint32_t kj = keys[j];
            rank += (kj < me) || (kj == me && j < t);
        }
        if (rank < FAN1) d_cols1[rank] = t;
    }
    __syncthreads();

    tf2x32(s2a, s2b, 0u, (uint32_t)t, b1, b2);
    keys[t] = b1 ^ b2;
    __syncthreads();
    {
        uint32_t me = keys[t];
        int rank = 0;
        #pragma unroll 8
        for (int j = 0; j < MAXDEG; j++) {
            uint32_t kj = keys[j];
            rank += (kj < me) || (kj == me && j < t);
        }
        if (rank < FAN2) d_cols2[rank] = t;
    }
}

// Build ids1[B*25] and ids2[B*250]
__global__ void build_ids_kernel(const int* __restrict__ ids,
                                 const int* __restrict__ adj) {
    int i = blockIdx.x * blockDim.x + threadIdx.x;
    if (i >= M1) return;
    int b = i / FAN1, s = i - b * FAN1;
    int id0 = ids[b];
    int id1 = adj[(size_t)id0 * MAXDEG + d_cols1[s]];
    d_ids1[i] = id1;
    const int* arow = adj + (size_t)id1 * MAXDEG;
    #pragma unroll
    for (int j = 0; j < FAN2; j++) {
        d_ids2[(size_t)i * FAN2 + j] = arow[d_cols2[j]];
    }
}

// one-shot fp16 hi/lo split of the 4 weight matrices, [n][k] half2-packed
__global__ void split_w_kernel(const float* __restrict__ W1x,
                               const float* __restrict__ W1n,
                               const float* __restrict__ W2x,
                               const float* __restrict__ W2n) {
    int m = blockIdx.y;
    const float* W = (m == 0) ? W1x : (m == 1) ? W1n : (m == 2) ? W2x : W2n;
    int i = blockIdx.x * blockDim.x + threadIdx.x;   // half2-pair index
    if (i < WSZH) {
        float w0 = W[2 * i], w1 = W[2 * i + 1];
        __half h0 = __float2half_rn(w0), h1 = __float2half_rn(w1);
        float l0 = w0 - __half2float(h0);
        float l1 = w1 - __half2float(h1);
        __half2 hh = __halves2half2(h0, h1);
        __half2 ll = __floats2half2_rn(l0, l1);
        d_Whh[(size_t)m * WSZH + i] = *(uint32_t*)&hh;
        d_Wll[(size_t)m * WSZH + i] = *(uint32_t*)&ll;
    }
}

#define MMA_F16(d, a0, a1, a2, a3, b0, b1) \
    asm volatile( \
        "mma.sync.aligned.m16n8k16.row.col.f32.f16.f16.f32 " \
        "{%0,%1,%2,%3}, {%4,%5,%6,%7}, {%8,%9}, {%0,%1,%2,%3};" \
        : "+f"((d)[0]), "+f"((d)[1]), "+f"((d)[2]), "+f"((d)[3]) \
        : "r"(a0), "r"(a1), "r"(a2), "r"(a3), "r"(b0), "r"(b1))

// ---------------- tensor-core fused gather(-mean)-GEMM (fp16 split) ----------
// gridDim.y = 2 selects branch (A-src, gather idx, weight, bias, column half).
// Branch 1 fuses an NM-row gather-mean into the A load when NM>1
// (gidx==null -> contiguous NM-groups). C[row, b*128+c] = act(A_b@W_b^T + bias).
// Template: NM = fused mean width; WM = warps in M (BM = 32*WM);
//           NPASS = 2 (A-compensated) or 3 (A- and B-compensated).
// 256 threads, N=128, K=256 in 4 chunks of 64.
// smem half2-words, row stride 36 (== 4 mod 32: conflict-free fragments).
#define KCH   64
#define STR   36

template <int NM, int WM, int NPASS>
__global__ __launch_bounds__(256, 3)
void gemm_tc_kernel(const float* __restrict__ A0, const int* __restrict__ g0,
                    const float* __restrict__ A1, const int* __restrict__ g1,
                    int wsel0, int wsel1,
                    const float* __restrict__ bias0, const float* __restrict__ bias1,
                    float* __restrict__ C, int do_relu) {
    constexpr int BM = 32 * WM;
    extern __shared__ uint32_t smx[];
    uint32_t* Ash = smx;
    uint32_t* Asl = smx + BM * STR;
    uint32_t* Bsh = smx + 2 * BM * STR;
    uint32_t* Bsl = smx + 2 * BM * STR + OUTD * STR;
    __shared__ int rowidx[BM];

    int branch = blockIdx.y;
    const float* Asrc = branch ? A1 : A0;
    const int*   gidx = branch ? g1 : g0;
    const uint32_t* Wh = d_Whh + (size_t)(branch ? wsel1 : wsel0) * WSZH;
    const uint32_t* Wl = d_Wll + (size_t)(branch ? wsel1 : wsel0) * WSZH;
    const float* bias = branch ? bias1 : bias0;
    int coloff = branch * OUTD;
    bool meanpath = (branch == 1) && (NM > 1);

    int t = threadIdx.x;
    int row0 = blockIdx.x * BM;
    if (!meanpath && t < BM) rowidx[t] = gidx ? gidx[row0 + t] : (row0 + t);
    __syncthreads();

    int wid = t >> 5, lane = t & 31;
    int wm = wid % WM;              // M slab (32 rows per warp)
    int wn = wid / WM;              // N slab (16*WM cols per warp)
    int qp = lane >> 2;             // 0..7
    int qi = lane & 3;              // 0..3
    constexpr int NT = 2 * WM;      // 8-col tiles per warp

    float acc[2][NT][4];
    #pragma unroll
    for (int mt = 0; mt < 2; mt++)
        #pragma unroll
        for (int nt = 0; nt < NT; nt++)
            #pragma unroll
            for (int j = 0; j < 4; j++) acc[mt][nt][j] = 0.f;

    for (int kc = 0; kc < 4; kc++) {
        // ---- A chunk: BM rows x 64 k = BM*16 float4 / 256 thr
        #pragma unroll
        for (int i = 0; i < 2 * WM; i++) {
            int idx = t + i * 256;
            int r  = idx >> 4;
            int k4 = idx & 15;
            float4 v;
            if (!meanpath) {
                v = *(const float4*)(Asrc + (size_t)rowidx[r] * DFEAT
                                     + kc * KCH + k4 * 4);
            } else {
                const int* gr = gidx ? (gidx + (size_t)(row0 + r) * NM) : nullptr;
                float4 s = make_float4(0.f, 0.f, 0.f, 0.f);
                #pragma unroll
                for (int j = 0; j < NM; j++) {
                    int src = gr ? __ldg(gr + j) : ((row0 + r) * NM + j);
                    const float4 u = *(const float4*)(Asrc + (size_t)src * DFEAT
                                                      + kc * KCH + k4 * 4);
                    s.x += u.x; s.y += u.y; s.z += u.z; s.w += u.w;
                }
                const float inv = 1.0f / NM;
                v = make_float4(s.x * inv, s.y * inv, s.z * inv, s.w * inv);
            }
            __half2 h01 = __floats2half2_rn(v.x, v.y);
            __half2 h23 = __floats2half2_rn(v.z, v.w);
            float2 f01 = __half22float2(h01);
            float2 f23 = __half22float2(h23);
            __half2 l01 = __floats2half2_rn(v.x - f01.x, v.y - f01.y);
            __half2 l23 = __floats2half2_rn(v.z - f23.x, v.w - f23.y);
            uint2 hw, lw;
            hw.x = *(uint32_t*)&h01; hw.y = *(uint32_t*)&h23;
            lw.x = *(uint32_t*)&l01; lw.y = *(uint32_t*)&l23;
            *(uint2*)(Ash + r * STR + k4 * 2) = hw;
            *(uint2*)(Asl + r * STR + k4 * 2) = lw;
        }
        // ---- B chunk (pre-split): 128 rows x 32 half2-words -> 4 uint4 each
        #pragma unroll
        for (int i = 0; i < 4; i++) {
            int idx = t + i * 256;
            int r  = idx >> 3;
            int w4 = idx & 7;
            *(uint4*)(Bsh + r * STR + w4 * 4) =
                *(const uint4*)(Wh + (size_t)r * (DFEAT / 2) + kc * (KCH / 2) + w4 * 4);
            if (NPASS >= 3)
                *(uint4*)(Bsl + r * STR + w4 * 4) =
                    *(const uint4*)(Wl + (size_t)r * (DFEAT / 2) + kc * (KCH / 2) + w4 * 4);
        }
        __syncthreads();

        #pragma unroll
        for (int kk2 = 0; kk2 < KCH / 2; kk2 += 8) {   // one m16n8k16 per step
            uint32_t ah[2][4], al[2][4];
            #pragma unroll
            for (int mt = 0; mt < 2; mt++) {
                int rm = wm * 32 + mt * 16 + qp;
                ah[mt][0] = Ash[rm * STR + kk2 + qi];
                ah[mt][1] = Ash[(rm + 8) * STR + kk2 + qi];
                ah[mt][2] = Ash[rm * STR + kk2 + qi + 4];
                ah[mt][3] = Ash[(rm + 8) * STR + kk2 + qi + 4];
                al[mt][0] = Asl[rm * STR + kk2 + qi];
                al[mt][1] = Asl[(rm + 8) * STR + kk2 + qi];
                al[mt][2] = Asl[rm * STR + kk2 + qi + 4];
                al[mt][3] = Asl[(rm + 8) * STR + kk2 + qi + 4];
            }
            #pragma unroll
            for (int nt = 0; nt < NT; nt++) {
                int nb = wn * (16 * WM) + nt * 8 + qp;
                uint32_t bh0 = Bsh[nb * STR + kk2 + qi];
                uint32_t bh1 = Bsh[nb * STR + kk2 + qi + 4];
                #pragma unroll
                for (int mt = 0; mt < 2; mt++) {
                    MMA_F16(acc[mt][nt], ah[mt][0], ah[mt][1], ah[mt][2], ah[mt][3], bh0, bh1);
                    MMA_F16(acc[mt][nt], al[mt][0], al[mt][1], al[mt][2], al[mt][3], bh0, bh1);
                    if (NPASS >= 3) {
                        uint32_t bl0 = Bsl[nb * STR + kk2 + qi];
                        uint32_t bl1 = Bsl[nb * STR + kk2 + qi + 4];
                        MMA_F16(acc[mt][nt], ah[mt][0], ah[mt][1], ah[mt][2], ah[mt][3], bl0, bl1);
                    }
                }
            }
        }
        __syncthreads();
    }

    // ---- epilogue: bias + optional relu, write to C (row stride 2*OUTD)
    #pragma unroll
    for (int nt = 0; nt < NT; nt++) {
        int col = wn * (16 * WM) + nt * 8 + 2 * qi;
        float bx = bias[col], by = bias[col + 1];
        #pragma unroll
        for (int mt = 0; mt < 2; mt++) {
            int r0 = row0 + wm * 32 + mt * 16 + qp;
            float v0 = acc[mt][nt][0] + bx;
            float v1 = acc[mt][nt][1] + by;
            float v2 = acc[mt][nt][2] + bx;
            float v3 = acc[mt][nt][3] + by;
            if (do_relu) {
                v0 = fmaxf(v0, 0.f); v1 = fmaxf(v1, 0.f);
                v2 = fmaxf(v2, 0.f); v3 = fmaxf(v3, 0.f);
            }
            *(float2*)(C + (size_t)r0 * (2 * OUTD) + coloff + col)       = make_float2(v0, v1);
            *(float2*)(C + (size_t)(r0 + 8) * (2 * OUTD) + coloff + col) = make_float2(v2, v3);
        }
    }
}

// ---------------- host launcher ----------------
extern "C" void kernel_launch(void* const* d_in, const int* in_sizes, int n_in,
                              void* d_out, int out_size) {
    const int*   ids   = (const int*)d_in[0];
    const int*   adj   = (const int*)d_in[1];
    const float* feats = (const float*)d_in[2];
    const float* W1x   = (const float*)d_in[3];
    const float* b1x   = (const float*)d_in[4];
    const float* W1n   = (const float*)d_in[5];
    const float* b1n   = (const float*)d_in[6];
    const float* W2x   = (const float*)d_in[7];
    const float* b2x   = (const float*)d_in[8];
    const float* W2n   = (const float*)d_in[9];
    const float* b2n   = (const float*)d_in[10];
    float* out = (float*)d_out;

    float *p_z1, *p_z0;
    int *p_ids1, *p_ids2;
    cudaGetSymbolAddress((void**)&p_z1,  d_z1);
    cudaGetSymbolAddress((void**)&p_z0,  d_z0);
    cudaGetSymbolAddress((void**)&p_ids1, d_ids1);
    cudaGetSymbolAddress((void**)&p_ids2, d_ids2);

    const int SMEM_BIG   = (2 * 64 * STR + 2 * OUTD * STR) * 4;  // 55296 B
    const int SMEM_SMALL = (2 * 32 * STR + 2 * OUTD * STR) * 4;  // 46080 B
    cudaFuncSetAttribute(gemm_tc_kernel<10, 2, 2>,
                         cudaFuncAttributeMaxDynamicSharedMemorySize, SMEM_BIG);
    cudaFuncSetAttribute(gemm_tc_kernel<25, 1, 3>,
                         cudaFuncAttributeMaxDynamicSharedMemorySize, SMEM_SMALL);

    // 1. permutations (threefry, partitionable, bits1 ^ bits2)
    setup_perm_kernel<<<1, 128>>>();
    // 2. weight fp16 hi/lo split
    split_w_kernel<<<dim3(WSZH / 256, 4), 256>>>(W1x, W1n, W2x, W2n);
    // 3. neighbor id tables
    build_ids_kernel<<<(M1 + 255) / 256, 256>>>(ids, adj);
    // 4. z1 = relu([feats[ids1]@W1x^T | mean10(feats[ids2])@W1n^T] + b)
    //    (fan-10 mean fused; 2-pass fp16 split)
    gemm_tc_kernel<10, 2, 2><<<dim3(M1 / 64, 2), 256, SMEM_BIG>>>(
        feats, p_ids1, feats, p_ids2, 0, 1, b1x, b1n, p_z1, 1);
    // 5. z0 = relu([feats[ids]@W1x^T | mean25(feats[ids1])@W1n^T] + b)
    //    (fan-25 mean fused into branch 1; 3-pass)
    gemm_tc_kernel<25, 1, 3><<<dim3(BATCH / 32, 2), 256, SMEM_SMALL>>>(
        feats, ids, feats, p_ids1, 0, 1, b1x, b1n, p_z0, 1);
    // 6. out = [z0@W2x^T + b2x | mean25(z1-groups)@W2n^T + b2n]   (no relu)
    //    (contiguous 25-group mean fused into branch 1; 3-pass)
    gemm_tc_kernel<25, 1, 3><<<dim3(BATCH / 32, 2), 256, SMEM_SMALL>>>(
        p_z0, nullptr, p_z1, nullptr, 2, 3, b2x, b2n, out, 0);
}

// round 9
// speedup vs baseline: 1.6970x; 1.6970x over previous
#include <cuda_runtime.h>
#include <cuda_fp16.h>
#include <cstdint>
#include <cstddef>

// ---------------- problem constants ----------------
#define NNODES   100000
#define DFEAT    256
#define MAXDEG   128
#define BATCH    1024
#define FAN1     25
#define FAN2     10
#define OUTD     128           // per-branch output
#define M1       (BATCH*FAN1)          // 25600
#define M2       (BATCH*FAN1*FAN2)     // 256000
#define WSZH     (OUTD * DFEAT / 2)    // half2 words per weight matrix = 16384

// ---------------- scratch (device globals; no allocation APIs) ----------------
__device__ int      d_cols1[FAN1];
__device__ int      d_cols2[FAN2];
__device__ int      d_ids1[M1];
__device__ int      d_ids2[M2];
__device__ float    d_z1[M1 * DFEAT];     // layer-1 output for ids1 rows
__device__ float    d_m1[BATCH * DFEAT];  // mean over fan1 of feats[ids1]
__device__ float    d_z0[BATCH * DFEAT];  // layer-1 output for ids rows
__device__ float    d_m3[BATCH * DFEAT];  // mean over fan1 of z1
__device__ uint32_t d_Whh[4 * WSZH];      // fp16 hi of weights, [n][k] half2-packed
__device__ uint32_t d_Wll[4 * WSZH];      // fp16 lo

// ---------------- threefry2x32 (JAX-exact, 20 rounds) ----------------
__device__ __forceinline__ uint32_t rotl32(uint32_t v, int r) {
    return (v << r) | (v >> (32 - r));
}

__device__ __forceinline__ void tf2x32(uint32_t k0, uint32_t k1,
                                       uint32_t x0, uint32_t x1,
                                       uint32_t& y0, uint32_t& y1) {
    uint32_t ks0 = k0, ks1 = k1, ks2 = k0 ^ k1 ^ 0x1BD11BDAu;
    x0 += ks0; x1 += ks1;
    const int r0[4] = {13, 15, 26, 6};
    const int r1[4] = {17, 29, 16, 24};
#define TF_G(RR) { x0 += x1; x1 = rotl32(x1, RR[0]); x1 ^= x0; \
                   x0 += x1; x1 = rotl32(x1, RR[1]); x1 ^= x0; \
                   x0 += x1; x1 = rotl32(x1, RR[2]); x1 ^= x0; \
                   x0 += x1; x1 = rotl32(x1, RR[3]); x1 ^= x0; }
    TF_G(r0); x0 += ks1; x1 += ks2 + 1u;
    TF_G(r1); x0 += ks2; x1 += ks0 + 2u;
    TF_G(r0); x0 += ks0; x1 += ks1 + 3u;
    TF_G(r1); x0 += ks1; x1 += ks2 + 4u;
    TF_G(r0); x0 += ks2; x1 += ks0 + 5u;
#undef TF_G
    y0 = x0; y1 = x1;
}

// jax.random.permutation(k, 128) for k1,k2 = split(key(42)),
// partitionable semantics; random_bits(32) = bits1 ^ bits2 (VERIFIED round 4)
__global__ void setup_perm_kernel() {
    int t = threadIdx.x;  // 128 threads
    uint32_t k1a, k1b, k2a, k2b;
    tf2x32(0u, 42u, 0u, 0u, k1a, k1b);
    tf2x32(0u, 42u, 0u, 1u, k2a, k2b);
    uint32_t s1a, s1b, s2a, s2b;
    tf2x32(k1a, k1b, 0u, 1u, s1a, s1b);
    tf2x32(k2a, k2b, 0u, 1u, s2a, s2b);

    __shared__ uint32_t keys[MAXDEG];
    uint32_t b1, b2;

    tf2x32(s1a, s1b, 0u, (uint32_t)t, b1, b2);
    keys[t] = b1 ^ b2;
    __syncthreads();
    {
        uint32_t me = keys[t];
        int rank = 0;
        #pragma unroll 8
        for (int j = 0; j < MAXDEG; j++) {
            uint32_t kj = keys[j];
            rank += (kj < me) || (kj == me && j < t);
        }
        if (rank < FAN1) d_cols1[rank] = t;
    }
    __syncthreads();

    tf2x32(s2a, s2b, 0u, (uint32_t)t, b1, b2);
    keys[t] = b1 ^ b2;
    __syncthreads();
    {
        uint32_t me = keys[t];
        int rank = 0;
        #pragma unroll 8
        for (int j = 0; j < MAXDEG; j++) {
            uint32_t kj = keys[j];
            rank += (kj < me) || (kj == me && j < t);
        }
        if (rank < FAN2) d_cols2[rank] = t;
    }
}

// Build ids1[B*25] and ids2[B*250]
__global__ void build_ids_kernel(const int* __restrict__ ids,
                                 const int* __restrict__ adj) {
    int i = blockIdx.x * blockDim.x + threadIdx.x;
    if (i >= M1) return;
    int b = i / FAN1, s = i - b * FAN1;
    int id0 = ids[b];
    int id1 = adj[(size_t)id0 * MAXDEG + d_cols1[s]];
    d_ids1[i] = id1;
    const int* arow = adj + (size_t)id1 * MAXDEG;
    #pragma unroll
    for (int j = 0; j < FAN2; j++) {
        d_ids2[(size_t)i * FAN2 + j] = arow[d_cols2[j]];
    }
}

// mean over NS rows, 4 output rows per block, float4 lanes (256 threads)
template <int NS>
__global__ void mean4_kernel(const float* __restrict__ src,
                             const int* __restrict__ idx,
                             float* __restrict__ out) {
    __shared__ int sidx[4][NS];
    int t = threadIdx.x;
    int row0 = blockIdx.x * 4;
    if (t < 4 * NS) {
        int rr = t / NS, jj = t - rr * NS;
        sidx[rr][jj] = idx ? idx[(size_t)(row0 + rr) * NS + jj]
                           : (row0 + rr) * NS + jj;
    }
    __syncthreads();
    int rr = t >> 6;
    int c4 = (t & 63) * 4;
    float4 s = make_float4(0.f, 0.f, 0.f, 0.f);
    #pragma unroll
    for (int j = 0; j < NS; j++) {
        const float4 v = *(const float4*)(src + (size_t)sidx[rr][j] * DFEAT + c4);
        s.x += v.x; s.y += v.y; s.z += v.z; s.w += v.w;
    }
    const float inv = 1.0f / NS;
    s.x *= inv; s.y *= inv; s.z *= inv; s.w *= inv;
    *(float4*)(out + (size_t)(row0 + rr) * DFEAT + c4) = s;
}

// one-shot fp16 hi/lo split of the 4 weight matrices, [n][k] half2-packed
__global__ void split_w_kernel(const float* __restrict__ W1x,
                               const float* __restrict__ W1n,
                               const float* __restrict__ W2x,
                               const float* __restrict__ W2n) {
    int m = blockIdx.y;
    const float* W = (m == 0) ? W1x : (m == 1) ? W1n : (m == 2) ? W2x : W2n;
    int i = blockIdx.x * blockDim.x + threadIdx.x;   // half2-pair index
    if (i < WSZH) {
        float w0 = W[2 * i], w1 = W[2 * i + 1];
        __half h0 = __float2half_rn(w0), h1 = __float2half_rn(w1);
        float l0 = w0 - __half2float(h0);
        float l1 = w1 - __half2float(h1);
        __half2 hh = __halves2half2(h0, h1);
        __half2 ll = __floats2half2_rn(l0, l1);
        d_Whh[(size_t)m * WSZH + i] = *(uint32_t*)&hh;
        d_Wll[(size_t)m * WSZH + i] = *(uint32_t*)&ll;
    }
}

#define MMA_F16(d, a0, a1, a2, a3, b0, b1) \
    asm volatile( \
        "mma.sync.aligned.m16n8k16.row.col.f32.f16.f16.f32 " \
        "{%0,%1,%2,%3}, {%4,%5,%6,%7}, {%8,%9}, {%0,%1,%2,%3};" \
        : "+f"((d)[0]), "+f"((d)[1]), "+f"((d)[2]), "+f"((d)[3]) \
        : "r"(a0), "r"(a1), "r"(a2), "r"(a3), "r"(b0), "r"(b1))

// ---------------- tensor-core fused gather(-mean)-GEMM (fp16 split) ----------
// gridDim.y = 2 selects branch (A-src, gather idx, weight, bias, column half).
// Branch 1 fuses an NM-row gather-mean into the A load when NM>1.
// Template: NM = fused mean width; WM = warps in M (BM = 32*WM);
//           NPASS = 2 (A-compensated only; Bsl unallocated) or 3.
// 256 threads, N=128, K=256 in 4 chunks of 64.
// smem half2-words, row stride 36 (== 4 mod 32: conflict-free fragments).
#define KCH   64
#define STR   36

template <int NM, int WM, int NPASS>
__global__ __launch_bounds__(256, (NPASS == 2 ? 4 : 3))
void gemm_tc_kernel(const float* __restrict__ A0, const int* __restrict__ g0,
                    const float* __restrict__ A1, const int* __restrict__ g1,
                    int wsel0, int wsel1,
                    const float* __restrict__ bias0, const float* __restrict__ bias1,
                    float* __restrict__ C, int do_relu) {
    constexpr int BM = 32 * WM;
    extern __shared__ uint32_t smx[];
    uint32_t* Ash = smx;
    uint32_t* Asl = smx + BM * STR;
    uint32_t* Bsh = smx + 2 * BM * STR;
    uint32_t* Bsl = smx + 2 * BM * STR + OUTD * STR;   // only valid if NPASS>=3
    __shared__ int rowidx[BM];

    int branch = blockIdx.y;
    const float* Asrc = branch ? A1 : A0;
    const int*   gidx = branch ? g1 : g0;
    const uint32_t* Wh = d_Whh + (size_t)(branch ? wsel1 : wsel0) * WSZH;
    const uint32_t* Wl = d_Wll + (size_t)(branch ? wsel1 : wsel0) * WSZH;
    const float* bias = branch ? bias1 : bias0;
    int coloff = branch * OUTD;
    bool meanpath = (branch == 1) && (NM > 1);

    int t = threadIdx.x;
    int row0 = blockIdx.x * BM;
    if (!meanpath && t < BM) rowidx[t] = gidx ? gidx[row0 + t] : (row0 + t);
    __syncthreads();

    int wid = t >> 5, lane = t & 31;
    int wm = wid % WM;              // M slab (32 rows per warp)
    int wn = wid / WM;              // N slab (16*WM cols per warp)
    int qp = lane >> 2;             // 0..7
    int qi = lane & 3;              // 0..3
    constexpr int NT = 2 * WM;      // 8-col tiles per warp

    float acc[2][NT][4];
    #pragma unroll
    for (int mt = 0; mt < 2; mt++)
        #pragma unroll
        for (int nt = 0; nt < NT; nt++)
            #pragma unroll
            for (int j = 0; j < 4; j++) acc[mt][nt][j] = 0.f;

    for (int kc = 0; kc < 4; kc++) {
        // ---- A chunk: BM rows x 64 k = BM*16 float4 / 256 thr
        #pragma unroll
        for (int i = 0; i < 2 * WM; i++) {
            int idx = t + i * 256;
            int r  = idx >> 4;
            int k4 = idx & 15;
            float4 v;
            if (!meanpath) {
                v = *(const float4*)(Asrc + (size_t)rowidx[r] * DFEAT
                                     + kc * KCH + k4 * 4);
            } else {
                const int* gr = gidx ? (gidx + (size_t)(row0 + r) * NM) : nullptr;
                float4 s = make_float4(0.f, 0.f, 0.f, 0.f);
                #pragma unroll
                for (int j = 0; j < NM; j++) {
                    int src = gr ? __ldg(gr + j) : ((row0 + r) * NM + j);
                    const float4 u = *(const float4*)(Asrc + (size_t)src * DFEAT
                                                      + kc * KCH + k4 * 4);
                    s.x += u.x; s.y += u.y; s.z += u.z; s.w += u.w;
                }
                const float inv = 1.0f / NM;
                v = make_float4(s.x * inv, s.y * inv, s.z * inv, s.w * inv);
            }
            __half2 h01 = __floats2half2_rn(v.x, v.y);
            __half2 h23 = __floats2half2_rn(v.z, v.w);
            float2 f01 = __half22float2(h01);
            float2 f23 = __half22float2(h23);
            __half2 l01 = __floats2half2_rn(v.x - f01.x, v.y - f01.y);
            __half2 l23 = __floats2half2_rn(v.z - f23.x, v.w - f23.y);
            uint2 hw, lw;
            hw.x = *(uint32_t*)&h01; hw.y = *(uint32_t*)&h23;
            lw.x = *(uint32_t*)&l01; lw.y = *(uint32_t*)&l23;
            *(uint2*)(Ash + r * STR + k4 * 2) = hw;
            *(uint2*)(Asl + r * STR + k4 * 2) = lw;
        }
        // ---- B chunk (pre-split): 128 rows x 32 half2-words -> 4 uint4 each
        #pragma unroll
        for (int i = 0; i < 4; i++) {
            int idx = t + i * 256;
            int r  = idx >> 3;
            int w4 = idx & 7;
            *(uint4*)(Bsh + r * STR + w4 * 4) =
                *(const uint4*)(Wh + (size_t)r * (DFEAT / 2) + kc * (KCH / 2) + w4 * 4);
            if (NPASS >= 3)
                *(uint4*)(Bsl + r * STR + w4 * 4) =
                    *(const uint4*)(Wl + (size_t)r * (DFEAT / 2) + kc * (KCH / 2) + w4 * 4);
        }
        __syncthreads();

        #pragma unroll
        for (int kk2 = 0; kk2 < KCH / 2; kk2 += 8) {   // one m16n8k16 per step
            uint32_t ah[2][4], al[2][4];
            #pragma unroll
            for (int mt = 0; mt < 2; mt++) {
                int rm = wm * 32 + mt * 16 + qp;
                ah[mt][0] = Ash[rm * STR + kk2 + qi];
                ah[mt][1] = Ash[(rm + 8) * STR + kk2 + qi];
                ah[mt][2] = Ash[rm * STR + kk2 + qi + 4];
                ah[mt][3] = Ash[(rm + 8) * STR + kk2 + qi + 4];
                al[mt][0] = Asl[rm * STR + kk2 + qi];
                al[mt][1] = Asl[(rm + 8) * STR + kk2 + qi];
                al[mt][2] = Asl[rm * STR + kk2 + qi + 4];
                al[mt][3] = Asl[(rm + 8) * STR + kk2 + qi + 4];
            }
            #pragma unroll
            for (int nt = 0; nt < NT; nt++) {
                int nb = wn * (16 * WM) + nt * 8 + qp;
                uint32_t bh0 = Bsh[nb * STR + kk2 + qi];
                uint32_t bh1 = Bsh[nb * STR + kk2 + qi + 4];
                #pragma unroll
                for (int mt = 0; mt < 2; mt++) {
                    MMA_F16(acc[mt][nt], ah[mt][0], ah[mt][1], ah[mt][2], ah[mt][3], bh0, bh1);
                    MMA_F16(acc[mt][nt], al[mt][0], al[mt][1], al[mt][2], al[mt][3], bh0, bh1);
                    if (NPASS >= 3) {
                        uint32_t bl0 = Bsl[nb * STR + kk2 + qi];
                        uint32_t bl1 = Bsl[nb * STR + kk2 + qi + 4];
                        MMA_F16(acc[mt][nt], ah[mt][0], ah[mt][1], ah[mt][2], ah[mt][3], bl0, bl1);
                    }
                }
            }
        }
        __syncthreads();
    }

    // ---- epilogue: bias + optional relu, write to C (row stride 2*OUTD)
    #pragma unroll
    for (int nt = 0; nt < NT; nt++) {
        int col = wn * (16 * WM) + nt * 8 + 2 * qi;
        float bx = bias[col], by = bias[col + 1];
        #pragma unroll
        for (int mt = 0; mt < 2; mt++) {
            int r0 = row0 + wm * 32 + mt * 16 + qp;
            float v0 = acc[mt][nt][0] + bx;
            float v1 = acc[mt][nt][1] + by;
            float v2 = acc[mt][nt][2] + bx;
            float v3 = acc[mt][nt][3] + by;
            if (do_relu) {
                v0 = fmaxf(v0, 0.f); v1 = fmaxf(v1, 0.f);
                v2 = fmaxf(v2, 0.f); v3 = fmaxf(v3, 0.f);
            }
            *(float2*)(C + (size_t)r0 * (2 * OUTD) + coloff + col)       = make_float2(v0, v1);
            *(float2*)(C + (size_t)(r0 + 8) * (2 * OUTD) + coloff + col) = make_float2(v2, v3);
        }
    }
}

// ---------------- host launcher ----------------
extern "C" void kernel_launch(void* const* d_in, const int* in_sizes, int n_in,
                              void* d_out, int out_size) {
    const int*   ids   = (const int*)d_in[0];
    const int*   adj   = (const int*)d_in[1];
    const float* feats = (const float*)d_in[2];
    const float* W1x   = (const float*)d_in[3];
    const float* b1x   = (const float*)d_in[4];
    const float* W1n   = (const float*)d_in[5];
    const float* b1n   = (const float*)d_in[6];
    const float* W2x   = (const float*)d_in[7];
    const float* b2x   = (const float*)d_in[8];
    const float* W2n   = (const float*)d_in[9];
    const float* b2n   = (const float*)d_in[10];
    float* out = (float*)d_out;

    float *p_z1, *p_m1, *p_z0, *p_m3;
    int *p_ids1, *p_ids2;
    cudaGetSymbolAddress((void**)&p_z1,  d_z1);
    cudaGetSymbolAddress((void**)&p_m1,  d_m1);
    cudaGetSymbolAddress((void**)&p_z0,  d_z0);
    cudaGetSymbolAddress((void**)&p_m3,  d_m3);
    cudaGetSymbolAddress((void**)&p_ids1, d_ids1);
    cudaGetSymbolAddress((void**)&p_ids2, d_ids2);

    // big kernel (NPASS=2): no Bsl buffer -> 2*64*36 + 128*36 = 9216 words
    const int SMEM_BIG   = (2 * 64 * STR + OUTD * STR) * 4;      // 36864 B
    const int SMEM_SMALL = (2 * 32 * STR + 2 * OUTD * STR) * 4;  // 46080 B
    cudaFuncSetAttribute(gemm_tc_kernel<10, 2, 2>,
                         cudaFuncAttributeMaxDynamicSharedMemorySize, SMEM_BIG);
    cudaFuncSetAttribute(gemm_tc_kernel<1, 1, 3>,
                         cudaFuncAttributeMaxDynamicSharedMemorySize, SMEM_SMALL);

    // 1. permutations (threefry, partitionable, bits1 ^ bits2)
    setup_perm_kernel<<<1, 128>>>();
    // 2. weight fp16 hi/lo split
    split_w_kernel<<<dim3(WSZH / 256, 4), 256>>>(W1x, W1n, W2x, W2n);
    // 3. neighbor id tables
    build_ids_kernel<<<(M1 + 255) / 256, 256>>>(ids, adj);
    // 4. m1 = mean_{fan1}(feats[ids1])   [1024,256]  (high-parallelism kernel)
    mean4_kernel<FAN1><<<BATCH / 4, 256>>>(feats, p_ids1, p_m1);
    // 5. z1 = relu([feats[ids1]@W1x^T | mean10(feats[ids2])@W1n^T] + b)
    //    (fan-10 mean fused into 800-CTA launch; 2-pass fp16 split, 4 CTAs/SM)
    gemm_tc_kernel<10, 2, 2><<<dim3(M1 / 64, 2), 256, SMEM_BIG>>>(
        feats, p_ids1, feats, p_ids2, 0, 1, b1x, b1n, p_z1, 1);
    // 6. z0 = relu([feats[ids]@W1x^T | m1@W1n^T] + b)   (plain loads, BM=32)
    gemm_tc_kernel<1, 1, 3><<<dim3(BATCH / 32, 2), 256, SMEM_SMALL>>>(
        feats, ids, p_m1, nullptr, 0, 1, b1x, b1n, p_z0, 1);
    // 7. m3 = mean_{fan1}(z1)   [1024,256]
    mean4_kernel<FAN1><<<BATCH / 4, 256>>>(p_z1, nullptr, p_m3);
    // 8. out = [z0@W2x^T + b2x | m3@W2n^T + b2n]   (no relu, BM=32)
    gemm_tc_kernel<1, 1, 3><<<dim3(BATCH / 32, 2), 256, SMEM_SMALL>>>(
        p_z0, nullptr, p_m3, nullptr, 2, 3, b2x, b2n, out, 0);
}

// round 10
// speedup vs baseline: 1.7289x; 1.0188x over previous
#include <cuda_runtime.h>
#include <cuda_fp16.h>
#include <cstdint>
#include <cstddef>

// ---------------- problem constants ----------------
#define NNODES   100000
#define DFEAT    256
#define MAXDEG   128
#define BATCH    1024
#define FAN1     25
#define FAN2     10
#define OUTD     128           // per-branch output
#define M1       (BATCH*FAN1)          // 25600
#define M2       (BATCH*FAN1*FAN2)     // 256000
#define WSZH     (OUTD * DFEAT / 2)    // half2 words per weight matrix = 16384

// ---------------- scratch (device globals; no allocation APIs) ----------------
__device__ int      d_cols1[FAN1];
__device__ int      d_cols2[FAN2];
__device__ int      d_ids1[M1];
__device__ int      d_ids2[M2];
__device__ float    d_z1[M1 * DFEAT];     // layer-1 output for ids1 rows
__device__ float    d_m1[BATCH * DFEAT];  // mean over fan1 of feats[ids1]
__device__ float    d_z0[BATCH * DFEAT];  // layer-1 output for ids rows
__device__ float    d_m3[BATCH * DFEAT];  // mean over fan1 of z1
__device__ uint32_t d_Whh[4 * WSZH];      // fp16 hi of weights, [n][k] half2-packed
__device__ uint32_t d_Wll[4 * WSZH];      // fp16 lo

// ---------------- threefry2x32 (JAX-exact, 20 rounds) ----------------
__device__ __forceinline__ uint32_t rotl32(uint32_t v, int r) {
    return (v << r) | (v >> (32 - r));
}

__device__ __forceinline__ void tf2x32(uint32_t k0, uint32_t k1,
                                       uint32_t x0, uint32_t x1,
                                       uint32_t& y0, uint32_t& y1) {
    uint32_t ks0 = k0, ks1 = k1, ks2 = k0 ^ k1 ^ 0x1BD11BDAu;
    x0 += ks0; x1 += ks1;
    const int r0[4] = {13, 15, 26, 6};
    const int r1[4] = {17, 29, 16, 24};
#define TF_G(RR) { x0 += x1; x1 = rotl32(x1, RR[0]); x1 ^= x0; \
                   x0 += x1; x1 = rotl32(x1, RR[1]); x1 ^= x0; \
                   x0 += x1; x1 = rotl32(x1, RR[2]); x1 ^= x0; \
                   x0 += x1; x1 = rotl32(x1, RR[3]); x1 ^= x0; }
    TF_G(r0); x0 += ks1; x1 += ks2 + 1u;
    TF_G(r1); x0 += ks2; x1 += ks0 + 2u;
    TF_G(r0); x0 += ks0; x1 += ks1 + 3u;
    TF_G(r1); x0 += ks1; x1 += ks2 + 4u;
    TF_G(r0); x0 += ks2; x1 += ks0 + 5u;
#undef TF_G
    y0 = x0; y1 = x1;
}

// jax.random.permutation(k, 128) for k1,k2 = split(key(42)),
// partitionable semantics; random_bits(32) = bits1 ^ bits2 (VERIFIED round 4)
__global__ void setup_perm_kernel() {
    int t = threadIdx.x;  // 128 threads
    uint32_t k1a, k1b, k2a, k2b;
    tf2x32(0u, 42u, 0u, 0u, k1a, k1b);
    tf2x32(0u, 42u, 0u, 1u, k2a, k2b);
    uint32_t s1a, s1b, s2a, s2b;
    tf2x32(k1a, k1b, 0u, 1u, s1a, s1b);
    tf2x32(k2a, k2b, 0u, 1u, s2a, s2b);

    __shared__ uint32_t keys[MAXDEG];
    uint32_t b1, b2;

    tf2x32(s1a, s1b, 0u, (uint32_t)t, b1, b2);
    keys[t] = b1 ^ b2;
    __syncthreads();
    {
        uint32_t me = keys[t];
        int rank = 0;
        #pragma unroll 8
        for (int j = 0; j < MAXDEG; j++) {
            uint32_t kj = keys[j];
            rank += (kj < me) || (kj == me && j < t);
        }
        if (rank < FAN1) d_cols1[rank] = t;
    }
    __syncthreads();

    tf2x32(s2a, s2b, 0u, (uint32_t)t, b1, b2);
    keys[t] = b1 ^ b2;
    __syncthreads();
    {
        uint32_t me = keys[t];
        int rank = 0;
        #pragma unroll 8
        for (int j = 0; j < MAXDEG; j++) {
            uint32_t kj = keys[j];
            rank += (kj < me) || (kj == me && j < t);
        }
        if (rank < FAN2) d_cols2[rank] = t;
    }
}

// Build ids1[B*25] and ids2[B*250]
__global__ void build_ids_kernel(const int* __restrict__ ids,
                                 const int* __restrict__ adj) {
    int i = blockIdx.x * blockDim.x + threadIdx.x;
    if (i >= M1) return;
    int b = i / FAN1, s = i - b * FAN1;
    int id0 = ids[b];
    int id1 = adj[(size_t)id0 * MAXDEG + d_cols1[s]];
    d_ids1[i] = id1;
    const int* arow = adj + (size_t)id1 * MAXDEG;
    #pragma unroll
    for (int j = 0; j < FAN2; j++) {
        d_ids2[(size_t)i * FAN2 + j] = arow[d_cols2[j]];
    }
}

// mean over NS rows, 4 output rows per block, float4 lanes (256 threads)
template <int NS>
__global__ void mean4_kernel(const float* __restrict__ src,
                             const int* __restrict__ idx,
                             float* __restrict__ out) {
    __shared__ int sidx[4][NS];
    int t = threadIdx.x;
    int row0 = blockIdx.x * 4;
    if (t < 4 * NS) {
        int rr = t / NS, jj = t - rr * NS;
        sidx[rr][jj] = idx ? idx[(size_t)(row0 + rr) * NS + jj]
                           : (row0 + rr) * NS + jj;
    }
    __syncthreads();
    int rr = t >> 6;
    int c4 = (t & 63) * 4;
    float4 s = make_float4(0.f, 0.f, 0.f, 0.f);
    #pragma unroll
    for (int j = 0; j < NS; j++) {
        const float4 v = *(const float4*)(src + (size_t)sidx[rr][j] * DFEAT + c4);
        s.x += v.x; s.y += v.y; s.z += v.z; s.w += v.w;
    }
    const float inv = 1.0f / NS;
    s.x *= inv; s.y *= inv; s.z *= inv; s.w *= inv;
    *(float4*)(out + (size_t)(row0 + rr) * DFEAT + c4) = s;
}

// one-shot fp16 hi/lo split of the 4 weight matrices, [n][k] half2-packed
__global__ void split_w_kernel(const float* __restrict__ W1x,
                               const float* __restrict__ W1n,
                               const float* __restrict__ W2x,
                               const float* __restrict__ W2n) {
    int m = blockIdx.y;
    const float* W = (m == 0) ? W1x : (m == 1) ? W1n : (m == 2) ? W2x : W2n;
    int i = blockIdx.x * blockDim.x + threadIdx.x;   // half2-pair index
    if (i < WSZH) {
        float w0 = W[2 * i], w1 = W[2 * i + 1];
        __half h0 = __float2half_rn(w0), h1 = __float2half_rn(w1);
        float l0 = w0 - __half2float(h0);
        float l1 = w1 - __half2float(h1);
        __half2 hh = __halves2half2(h0, h1);
        __half2 ll = __floats2half2_rn(l0, l1);
        d_Whh[(size_t)m * WSZH + i] = *(uint32_t*)&hh;
        d_Wll[(size_t)m * WSZH + i] = *(uint32_t*)&ll;
    }
}

#define MMA_F16(d, a0, a1, a2, a3, b0, b1) \
    asm volatile( \
        "mma.sync.aligned.m16n8k16.row.col.f32.f16.f16.f32 " \
        "{%0,%1,%2,%3}, {%4,%5,%6,%7}, {%8,%9}, {%0,%1,%2,%3};" \
        : "+f"((d)[0]), "+f"((d)[1]), "+f"((d)[2]), "+f"((d)[3]) \
        : "r"(a0), "r"(a1), "r"(a2), "r"(a3), "r"(b0), "r"(b1))

#define LDSM_X4(r0, r1, r2, r3, addr) \
    asm volatile( \
        "ldmatrix.sync.aligned.m8n8.x4.shared.b16 {%0,%1,%2,%3}, [%4];" \
        : "=r"(r0), "=r"(r1), "=r"(r2), "=r"(r3) : "r"(addr))

// ---------------- tensor-core fused gather(-mean)-GEMM (fp16 split) ----------
// gridDim.y = 2 selects branch (A-src, gather idx, weight, bias, column half).
// Branch 1 fuses an NM-row gather-mean into the A load when NM>1.
// Template: NM = fused mean width; WM = warps in M (BM = 32*WM);
//           NPASS = 2 (A-compensated only; Bsl unallocated) or 3.
// 256 threads, N=128, K=256 in 4 chunks of 64.  Fragments via ldmatrix.
// smem half2-words, row stride 36 (== 4 mod 32: conflict-free LDSM phases).
#define KCH   64
#define STR   36

template <int NM, int WM, int NPASS>
__global__ __launch_bounds__(256, (NPASS == 2 ? 4 : 3))
void gemm_tc_kernel(const float* __restrict__ A0, const int* __restrict__ g0,
                    const float* __restrict__ A1, const int* __restrict__ g1,
                    int wsel0, int wsel1,
                    const float* __restrict__ bias0, const float* __restrict__ bias1,
                    float* __restrict__ C, int do_relu) {
    constexpr int BM = 32 * WM;
    extern __shared__ uint32_t smx[];
    uint32_t* Ash = smx;
    uint32_t* Asl = smx + BM * STR;
    uint32_t* Bsh = smx + 2 * BM * STR;
    uint32_t* Bsl = smx + 2 * BM * STR + OUTD * STR;   // only valid if NPASS>=3
    __shared__ int rowidx[BM];

    int branch = blockIdx.y;
    const float* Asrc = branch ? A1 : A0;
    const int*   gidx = branch ? g1 : g0;
    const uint32_t* Wh = d_Whh + (size_t)(branch ? wsel1 : wsel0) * WSZH;
    const uint32_t* Wl = d_Wll + (size_t)(branch ? wsel1 : wsel0) * WSZH;
    const float* bias = branch ? bias1 : bias0;
    int coloff = branch * OUTD;
    bool meanpath = (branch == 1) && (NM > 1);

    int t = threadIdx.x;
    int row0 = blockIdx.x * BM;
    if (!meanpath && t < BM) rowidx[t] = gidx ? gidx[row0 + t] : (row0 + t);
    __syncthreads();

    int wid = t >> 5, lane = t & 31;
    int wm = wid % WM;              // M slab (32 rows per warp)
    int wn = wid / WM;              // N slab (16*WM cols per warp)
    int qp = lane >> 2;             // 0..7 (epilogue)
    int qi = lane & 3;              // 0..3 (epilogue)
    constexpr int NT = 2 * WM;      // 8-col tiles per warp

    // ---- ldmatrix base addresses (bytes; constant across k-chunks) ----
    uint32_t ash32 = (uint32_t)__cvta_generic_to_shared(Ash);
    uint32_t asl32 = (uint32_t)__cvta_generic_to_shared(Asl);
    uint32_t bsh32 = (uint32_t)__cvta_generic_to_shared(Bsh);
    uint32_t bsl32 = (uint32_t)__cvta_generic_to_shared(Bsl);
    // A: x4 matrices [a0: rows rm+0..7 klow | a1: rm+8..15 klow | a2/a3: khigh]
    uint32_t aoffA[2], aoffB;
    #pragma unroll
    for (int mt = 0; mt < 2; mt++)
        aoffA[mt] = (uint32_t)(((wm * 32 + mt * 16 + (lane & 15)) * STR
                                + (lane >> 4) * 4) * 4);
    // B: x4 = [nt=2p klow | nt=2p khigh | nt=2p+1 klow | nt=2p+1 khigh]
    aoffB = (uint32_t)(((wn * (16 * WM) + (lane >> 4) * 8 + (lane & 7)) * STR
                        + ((lane >> 3) & 1) * 4) * 4);

    float acc[2][NT][4];
    #pragma unroll
    for (int mt = 0; mt < 2; mt++)
        #pragma unroll
        for (int nt = 0; nt < NT; nt++)
            #pragma unroll
            for (int j = 0; j < 4; j++) acc[mt][nt][j] = 0.f;

    for (int kc = 0; kc < 4; kc++) {
        // ---- A chunk: BM rows x 64 k = BM*16 float4 / 256 thr
        #pragma unroll
        for (int i = 0; i < 2 * WM; i++) {
            int idx = t + i * 256;
            int r  = idx >> 4;
            int k4 = idx & 15;
            float4 v;
            if (!meanpath) {
                v = *(const float4*)(Asrc + (size_t)rowidx[r] * DFEAT
                                     + kc * KCH + k4 * 4);
            } else {
                const int* gr = gidx ? (gidx + (size_t)(row0 + r) * NM) : nullptr;
                float4 s = make_float4(0.f, 0.f, 0.f, 0.f);
                #pragma unroll
                for (int j = 0; j < NM; j++) {
                    int src = gr ? __ldg(gr + j) : ((row0 + r) * NM + j);
                    const float4 u = *(const float4*)(Asrc + (size_t)src * DFEAT
                                                      + kc * KCH + k4 * 4);
                    s.x += u.x; s.y += u.y; s.z += u.z; s.w += u.w;
                }
                const float inv = 1.0f / NM;
                v = make_float4(s.x * inv, s.y * inv, s.z * inv, s.w * inv);
            }
            __half2 h01 = __floats2half2_rn(v.x, v.y);
            __half2 h23 = __floats2half2_rn(v.z, v.w);
            float2 f01 = __half22float2(h01);
            float2 f23 = __half22float2(h23);
            __half2 l01 = __floats2half2_rn(v.x - f01.x, v.y - f01.y);
            __half2 l23 = __floats2half2_rn(v.z - f23.x, v.w - f23.y);
            uint2 hw, lw;
            hw.x = *(uint32_t*)&h01; hw.y = *(uint32_t*)&h23;
            lw.x = *(uint32_t*)&l01; lw.y = *(uint32_t*)&l23;
            *(uint2*)(Ash + r * STR + k4 * 2) = hw;
            *(uint2*)(Asl + r * STR + k4 * 2) = lw;
        }
        // ---- B chunk (pre-split): 128 rows x 32 half2-words -> 4 uint4 each
        #pragma unroll
        for (int i = 0; i < 4; i++) {
            int idx = t + i * 256;
            int r  = idx >> 3;
            int w4 = idx & 7;
            *(uint4*)(Bsh + r * STR + w4 * 4) =
                *(const uint4*)(Wh + (size_t)r * (DFEAT / 2) + kc * (KCH / 2) + w4 * 4);
            if (NPASS >= 3)
                *(uint4*)(Bsl + r * STR + w4 * 4) =
                    *(const uint4*)(Wl + (size_t)r * (DFEAT / 2) + kc * (KCH / 2) + w4 * 4);
        }
        __syncthreads();

        #pragma unroll
        for (int kk2 = 0; kk2 < KCH / 2; kk2 += 8) {   // one m16n8k16 per step
            uint32_t kb = (uint32_t)(kk2 * 4);         // byte offset for this step
            uint32_t ah[2][4], al[2][4];
            #pragma unroll
            for (int mt = 0; mt < 2; mt++) {
                LDSM_X4(ah[mt][0], ah[mt][1], ah[mt][2], ah[mt][3],
                        ash32 + aoffA[mt] + kb);
                LDSM_X4(al[mt][0], al[mt][1], al[mt][2], al[mt][3],
                        asl32 + aoffA[mt] + kb);
            }
            #pragma unroll
            for (int p = 0; p < WM; p++) {
                uint32_t pboff = aoffB + (uint32_t)(p * 16 * STR * 4);
                uint32_t bh0, bh1, bh2, bh3;
                LDSM_X4(bh0, bh1, bh2, bh3, bsh32 + pboff + kb);
                #pragma unroll
                for (int mt = 0; mt < 2; mt++) {
                    MMA_F16(acc[mt][2 * p],     ah[mt][0], ah[mt][1], ah[mt][2], ah[mt][3], bh0, bh1);
                    MMA_F16(acc[mt][2 * p],     al[mt][0], al[mt][1], al[mt][2], al[mt][3], bh0, bh1);
                    MMA_F16(acc[mt][2 * p + 1], ah[mt][0], ah[mt][1], ah[mt][2], ah[mt][3], bh2, bh3);
                    MMA_F16(acc[mt][2 * p + 1], al[mt][0], al[mt][1], al[mt][2], al[mt][3], bh2, bh3);
                }
                if (NPASS >= 3) {
                    uint32_t bl0, bl1, bl2, bl3;
                    LDSM_X4(bl0, bl1, bl2, bl3, bsl32 + pboff + kb);
                    #pragma unroll
                    for (int mt = 0; mt < 2; mt++) {
                        MMA_F16(acc[mt][2 * p],     ah[mt][0], ah[mt][1], ah[mt][2], ah[mt][3], bl0, bl1);
                        MMA_F16(acc[mt][2 * p + 1], ah[mt][0], ah[mt][1], ah[mt][2], ah[mt][3], bl2, bl3);
                    }
                }
            }
        }
        __syncthreads();
    }

    // ---- epilogue: bias + optional relu, write to C (row stride 2*OUTD)
    #pragma unroll
    for (int nt = 0; nt < NT; nt++) {
        int col = wn * (16 * WM) + nt * 8 + 2 * qi;
        float bx = bias[col], by = bias[col + 1];
        #pragma unroll
        for (int mt = 0; mt < 2; mt++) {
            int r0 = row0 + wm * 32 + mt * 16 + qp;
            float v0 = acc[mt][nt][0] + bx;
            float v1 = acc[mt][nt][1] + by;
            float v2 = acc[mt][nt][2] + bx;
            float v3 = acc[mt][nt][3] + by;
            if (do_relu) {
                v0 = fmaxf(v0, 0.f); v1 = fmaxf(v1, 0.f);
                v2 = fmaxf(v2, 0.f); v3 = fmaxf(v3, 0.f);
            }
            *(float2*)(C + (size_t)r0 * (2 * OUTD) + coloff + col)       = make_float2(v0, v1);
            *(float2*)(C + (size_t)(r0 + 8) * (2 * OUTD) + coloff + col) = make_float2(v2, v3);
        }
    }
}

// ---------------- host launcher ----------------
extern "C" void kernel_launch(void* const* d_in, const int* in_sizes, int n_in,
                              void* d_out, int out_size) {
    const int*   ids   = (const int*)d_in[0];
    const int*   adj   = (const int*)d_in[1];
    const float* feats = (const float*)d_in[2];
    const float* W1x   = (const float*)d_in[3];
    const float* b1x   = (const float*)d_in[4];
    const float* W1n   = (const float*)d_in[5];
    const float* b1n   = (const float*)d_in[6];
    const float* W2x   = (const float*)d_in[7];
    const float* b2x   = (const float*)d_in[8];
    const float* W2n   = (const float*)d_in[9];
    const float* b2n   = (const float*)d_in[10];
    float* out = (float*)d_out;

    float *p_z1, *p_m1, *p_z0, *p_m3;
    int *p_ids1, *p_ids2;
    cudaGetSymbolAddress((void**)&p_z1,  d_z1);
    cudaGetSymbolAddress((void**)&p_m1,  d_m1);
    cudaGetSymbolAddress((void**)&p_z0,  d_z0);
    cudaGetSymbolAddress((void**)&p_m3,  d_m3);
    cudaGetSymbolAddress((void**)&p_ids1, d_ids1);
    cudaGetSymbolAddress((void**)&p_ids2, d_ids2);

    // big kernel (NPASS=2): no Bsl buffer -> 2*64*36 + 128*36 = 9216 words
    const int SMEM_BIG   = (2 * 64 * STR + OUTD * STR) * 4;      // 36864 B
    const int SMEM_SMALL = (2 * 32 * STR + 2 * OUTD * STR) * 4;  // 46080 B
    cudaFuncSetAttribute(gemm_tc_kernel<10, 2, 2>,
                         cudaFuncAttributeMaxDynamicSharedMemorySize, SMEM_BIG);
    cudaFuncSetAttribute(gemm_tc_kernel<1, 1, 3>,
                         cudaFuncAttributeMaxDynamicSharedMemorySize, SMEM_SMALL);

    // 1. permutations (threefry, partitionable, bits1 ^ bits2)
    setup_perm_kernel<<<1, 128>>>();
    // 2. weight fp16 hi/lo split
    split_w_kernel<<<dim3(WSZH / 256, 4), 256>>>(W1x, W1n, W2x, W2n);
    // 3. neighbor id tables
    build_ids_kernel<<<(M1 + 255) / 256, 256>>>(ids, adj);
    // 4. m1 = mean_{fan1}(feats[ids1])   [1024,256]  (high-parallelism kernel)
    mean4_kernel<FAN1><<<BATCH / 4, 256>>>(feats, p_ids1, p_m1);
    // 5. z1 = relu([feats[ids1]@W1x^T | mean10(feats[ids2])@W1n^T] + b)
    //    (fan-10 mean fused into 800-CTA launch; 2-pass fp16 split, 4 CTAs/SM)
    gemm_tc_kernel<10, 2, 2><<<dim3(M1 / 64, 2), 256, SMEM_BIG>>>(
        feats, p_ids1, feats, p_ids2, 0, 1, b1x, b1n, p_z1, 1);
    // 6. z0 = relu([feats[ids]@W1x^T | m1@W1n^T] + b)   (plain loads, BM=32)
    gemm_tc_kernel<1, 1, 3><<<dim3(BATCH / 32, 2), 256, SMEM_SMALL>>>(
        feats, ids, p_m1, nullptr, 0, 1, b1x, b1n, p_z0, 1);
    // 7. m3 = mean_{fan1}(z1)   [1024,256]
    mean4_kernel<FAN1><<<BATCH / 4, 256>>>(p_z1, nullptr, p_m3);
    // 8. out = [z0@W2x^T + b2x | m3@W2n^T + b2n]   (no relu, BM=32)
    gemm_tc_kernel<1, 1, 3><<<dim3(BATCH / 32, 2), 256, SMEM_SMALL>>>(
        p_z0, nullptr, p_m3, nullptr, 2, 3, b2x, b2n, out, 0);
}

// round 11
// speedup vs baseline: 1.7294x; 1.0003x over previous
#include <cuda_runtime.h>
#include <cuda_fp16.h>
#include <cstdint>
#include <cstddef>

// ---------------- problem constants ----------------
#define NNODES   100000
#define DFEAT    256
#define MAXDEG   128
#define BATCH    1024
#define FAN1     25
#define FAN2     10
#define OUTD     128           // per-branch output
#define M1       (BATCH*FAN1)          // 25600
#define M2       (BATCH*FAN1*FAN2)     // 256000
#define WSZH     (OUTD * DFEAT / 2)    // half2 words per weight matrix = 16384

// ---------------- scratch (device globals; no allocation APIs) ----------------
__device__ int      d_cols1[FAN1];
__device__ int      d_cols2[FAN2];
__device__ int      d_ids1[M1];
__device__ int      d_ids2[M2];
__device__ float    d_m2[M1 * DFEAT];     // mean over fan2 of feats[ids2]
__device__ float    d_z1[M1 * DFEAT];     // layer-1 output for ids1 rows
__device__ float    d_m1[BATCH * DFEAT];  // mean over fan1 of feats[ids1]
__device__ float    d_z0[BATCH * DFEAT];  // layer-1 output for ids rows
__device__ float    d_m3[BATCH * DFEAT];  // mean over fan1 of z1
__device__ uint32_t d_Whh[4 * WSZH];      // fp16 hi of weights, [n][k] half2-packed
__device__ uint32_t d_Wll[4 * WSZH];      // fp16 lo

// ---------------- threefry2x32 (JAX-exact, 20 rounds) ----------------
__device__ __forceinline__ uint32_t rotl32(uint32_t v, int r) {
    return (v << r) | (v >> (32 - r));
}

__device__ __forceinline__ void tf2x32(uint32_t k0, uint32_t k1,
                                       uint32_t x0, uint32_t x1,
                                       uint32_t& y0, uint32_t& y1) {
    uint32_t ks0 = k0, ks1 = k1, ks2 = k0 ^ k1 ^ 0x1BD11BDAu;
    x0 += ks0; x1 += ks1;
    const int r0[4] = {13, 15, 26, 6};
    const int r1[4] = {17, 29, 16, 24};
#define TF_G(RR) { x0 += x1; x1 = rotl32(x1, RR[0]); x1 ^= x0; \
                   x0 += x1; x1 = rotl32(x1, RR[1]); x1 ^= x0; \
                   x0 += x1; x1 = rotl32(x1, RR[2]); x1 ^= x0; \
                   x0 += x1; x1 = rotl32(x1, RR[3]); x1 ^= x0; }
    TF_G(r0); x0 += ks1; x1 += ks2 + 1u;
    TF_G(r1); x0 += ks2; x1 += ks0 + 2u;
    TF_G(r0); x0 += ks0; x1 += ks1 + 3u;
    TF_G(r1); x0 += ks1; x1 += ks2 + 4u;
    TF_G(r0); x0 += ks2; x1 += ks0 + 5u;
#undef TF_G
    y0 = x0; y1 = x1;
}

// jax.random.permutation(k, 128) for k1,k2 = split(key(42)),
// partitionable semantics; random_bits(32) = bits1 ^ bits2 (VERIFIED round 4)
__global__ void setup_perm_kernel() {
    int t = threadIdx.x;  // 128 threads
    uint32_t k1a, k1b, k2a, k2b;
    tf2x32(0u, 42u, 0u, 0u, k1a, k1b);
    tf2x32(0u, 42u, 0u, 1u, k2a, k2b);
    uint32_t s1a, s1b, s2a, s2b;
    tf2x32(k1a, k1b, 0u, 1u, s1a, s1b);
    tf2x32(k2a, k2b, 0u, 1u, s2a, s2b);

    __shared__ uint32_t keys[MAXDEG];
    uint32_t b1, b2;

    tf2x32(s1a, s1b, 0u, (uint32_t)t, b1, b2);
    keys[t] = b1 ^ b2;
    __syncthreads();
    {
        uint32_t me = keys[t];
        int rank = 0;
        #pragma unroll 8
        for (int j = 0; j < MAXDEG; j++) {
            uint32_t kj = keys[j];
            rank += (kj < me) || (kj == me && j < t);
        }
        if (rank < FAN1) d_cols1[rank] = t;
    }
    __syncthreads();

    tf2x32(s2a, s2b, 0u, (uint32_t)t, b1, b2);
    keys[t] = b1 ^ b2;
    __syncthreads();
    {
        uint32_t me = keys[t];
        int rank = 0;
        #pragma unroll 8
        for (int j = 0; j < MAXDEG; j++) {
            uint32_t kj = keys[j];
            rank += (kj < me) || (kj == me && j < t);
        }
        if (rank < FAN2) d_cols2[rank] = t;
    }
}

// Build ids1[B*25] and ids2[B*250]
__global__ void build_ids_kernel(const int* __restrict__ ids,
                                 const int* __restrict__ adj) {
    int i = blockIdx.x * blockDim.x + threadIdx.x;
    if (i >= M1) return;
    int b = i / FAN1, s = i - b * FAN1;
    int id0 = ids[b];
    int id1 = adj[(size_t)id0 * MAXDEG + d_cols1[s]];
    d_ids1[i] = id1;
    const int* arow = adj + (size_t)id1 * MAXDEG;
    #pragma unroll
    for (int j = 0; j < FAN2; j++) {
        d_ids2[(size_t)i * FAN2 + j] = arow[d_cols2[j]];
    }
}

// mean over NS rows, 4 output rows per block, float4 lanes (256 threads)
template <int NS>
__global__ void mean4_kernel(const float* __restrict__ src,
                             const int* __restrict__ idx,
                             float* __restrict__ out) {
    __shared__ int sidx[4][NS];
    int t = threadIdx.x;
    int row0 = blockIdx.x * 4;
    if (t < 4 * NS) {
        int rr = t / NS, jj = t - rr * NS;
        sidx[rr][jj] = idx ? idx[(size_t)(row0 + rr) * NS + jj]
                           : (row0 + rr) * NS + jj;
    }
    __syncthreads();
    int rr = t >> 6;
    int c4 = (t & 63) * 4;
    float4 s = make_float4(0.f, 0.f, 0.f, 0.f);
    #pragma unroll
    for (int j = 0; j < NS; j++) {
        const float4 v = *(const float4*)(src + (size_t)sidx[rr][j] * DFEAT + c4);
        s.x += v.x; s.y += v.y; s.z += v.z; s.w += v.w;
    }
    const float inv = 1.0f / NS;
    s.x *= inv; s.y *= inv; s.z *= inv; s.w *= inv;
    *(float4*)(out + (size_t)(row0 + rr) * DFEAT + c4) = s;
}

// one-shot fp16 hi/lo split of the 4 weight matrices, [n][k] half2-packed
__global__ void split_w_kernel(const float* __restrict__ W1x,
                               const float* __restrict__ W1n,
                               const float* __restrict__ W2x,
                               const float* __restrict__ W2n) {
    int m = blockIdx.y;
    const float* W = (m == 0) ? W1x : (m == 1) ? W1n : (m == 2) ? W2x : W2n;
    int i = blockIdx.x * blockDim.x + threadIdx.x;   // half2-pair index
    if (i < WSZH) {
        float w0 = W[2 * i], w1 = W[2 * i + 1];
        __half h0 = __float2half_rn(w0), h1 = __float2half_rn(w1);
        float l0 = w0 - __half2float(h0);
        float l1 = w1 - __half2float(h1);
        __half2 hh = __halves2half2(h0, h1);
        __half2 ll = __floats2half2_rn(l0, l1);
        d_Whh[(size_t)m * WSZH + i] = *(uint32_t*)&hh;
        d_Wll[(size_t)m * WSZH + i] = *(uint32_t*)&ll;
    }
}

#define MMA_F16(d, a0, a1, a2, a3, b0, b1) \
    asm volatile( \
        "mma.sync.aligned.m16n8k16.row.col.f32.f16.f16.f32 " \
        "{%0,%1,%2,%3}, {%4,%5,%6,%7}, {%8,%9}, {%0,%1,%2,%3};" \
        : "+f"((d)[0]), "+f"((d)[1]), "+f"((d)[2]), "+f"((d)[3]) \
        : "r"(a0), "r"(a1), "r"(a2), "r"(a3), "r"(b0), "r"(b1))

#define LDSM_X4(r0, r1, r2, r3, addr) \
    asm volatile( \
        "ldmatrix.sync.aligned.m8n8.x4.shared.b16 {%0,%1,%2,%3}, [%4];" \
        : "=r"(r0), "=r"(r1), "=r"(r2), "=r"(r3) : "r"(addr))

// ---------------- tensor-core fused gather(-mean)-GEMM (fp16 split) ----------
// gridDim.y = 2 selects branch (A-src, gather idx, weight, bias, column half).
// Branch 1 fuses an NM-row gather-mean into the A load when NM>1.
// Template: NM = fused mean width; WM = warps in M (BM = 32*WM);
//           NPASS = 2 (A-compensated only; Bsl unallocated) or 3.
// 256 threads, N=128, K=256 in 4 chunks of 64.  Fragments via ldmatrix.
// smem half2-words, row stride 36 (== 4 mod 32: conflict-free LDSM phases).
#define KCH   64
#define STR   36

template <int NM, int WM, int NPASS>
__global__ __launch_bounds__(256, (NPASS == 2 ? 4 : 3))
void gemm_tc_kernel(const float* __restrict__ A0, const int* __restrict__ g0,
                    const float* __restrict__ A1, const int* __restrict__ g1,
                    int wsel0, int wsel1,
                    const float* __restrict__ bias0, const float* __restrict__ bias1,
                    float* __restrict__ C, int do_relu) {
    constexpr int BM = 32 * WM;
    extern __shared__ uint32_t smx[];
    uint32_t* Ash = smx;
    uint32_t* Asl = smx + BM * STR;
    uint32_t* Bsh = smx + 2 * BM * STR;
    uint32_t* Bsl = smx + 2 * BM * STR + OUTD * STR;   // only valid if NPASS>=3
    __shared__ int rowidx[BM];

    int branch = blockIdx.y;
    const float* Asrc = branch ? A1 : A0;
    const int*   gidx = branch ? g1 : g0;
    const uint32_t* Wh = d_Whh + (size_t)(branch ? wsel1 : wsel0) * WSZH;
    const uint32_t* Wl = d_Wll + (size_t)(branch ? wsel1 : wsel0) * WSZH;
    const float* bias = branch ? bias1 : bias0;
    int coloff = branch * OUTD;
    bool meanpath = (branch == 1) && (NM > 1);

    int t = threadIdx.x;
    int row0 = blockIdx.x * BM;
    if (!meanpath && t < BM) rowidx[t] = gidx ? gidx[row0 + t] : (row0 + t);
    __syncthreads();

    int wid = t >> 5, lane = t & 31;
    int wm = wid % WM;              // M slab (32 rows per warp)
    int wn = wid / WM;              // N slab (16*WM cols per warp)
    int qp = lane >> 2;             // 0..7 (epilogue)
    int qi = lane & 3;              // 0..3 (epilogue)
    constexpr int NT = 2 * WM;      // 8-col tiles per warp

    // ---- ldmatrix base addresses (bytes; constant across k-chunks) ----
    uint32_t ash32 = (uint32_t)__cvta_generic_to_shared(Ash);
    uint32_t asl32 = (uint32_t)__cvta_generic_to_shared(Asl);
    uint32_t bsh32 = (uint32_t)__cvta_generic_to_shared(Bsh);
    uint32_t bsl32 = (uint32_t)__cvta_generic_to_shared(Bsl);
    // A: x4 matrices [a0: rows rm+0..7 klow | a1: rm+8..15 klow | a2/a3: khigh]
    uint32_t aoffA[2], aoffB;
    #pragma unroll
    for (int mt = 0; mt < 2; mt++)
        aoffA[mt] = (uint32_t)(((wm * 32 + mt * 16 + (lane & 15)) * STR
                                + (lane >> 4) * 4) * 4);
    // B: x4 = [nt=2p klow | nt=2p khigh | nt=2p+1 klow | nt=2p+1 khigh]
    aoffB = (uint32_t)(((wn * (16 * WM) + (lane >> 4) * 8 + (lane & 7)) * STR
                        + ((lane >> 3) & 1) * 4) * 4);

    float acc[2][NT][4];
    #pragma unroll
    for (int mt = 0; mt < 2; mt++)
        #pragma unroll
        for (int nt = 0; nt < NT; nt++)
            #pragma unroll
            for (int j = 0; j < 4; j++) acc[mt][nt][j] = 0.f;

    for (int kc = 0; kc < 4; kc++) {
        // ---- A chunk: BM rows x 64 k = BM*16 float4 / 256 thr
        #pragma unroll
        for (int i = 0; i < 2 * WM; i++) {
            int idx = t + i * 256;
            int r  = idx >> 4;
            int k4 = idx & 15;
            float4 v;
            if (!meanpath) {
                v = *(const float4*)(Asrc + (size_t)rowidx[r] * DFEAT
                                     + kc * KCH + k4 * 4);
            } else {
                const int* gr = gidx ? (gidx + (size_t)(row0 + r) * NM) : nullptr;
                float4 s = make_float4(0.f, 0.f, 0.f, 0.f);
                #pragma unroll
                for (int j = 0; j < NM; j++) {
                    int src = gr ? __ldg(gr + j) : ((row0 + r) * NM + j);
                    const float4 u = *(const float4*)(Asrc + (size_t)src * DFEAT
                                                      + kc * KCH + k4 * 4);
                    s.x += u.x; s.y += u.y; s.z += u.z; s.w += u.w;
                }
                const float inv = 1.0f / NM;
                v = make_float4(s.x * inv, s.y * inv, s.z * inv, s.w * inv);
            }
            __half2 h01 = __floats2half2_rn(v.x, v.y);
            __half2 h23 = __floats2half2_rn(v.z, v.w);
            float2 f01 = __half22float2(h01);
            float2 f23 = __half22float2(h23);
            __half2 l01 = __floats2half2_rn(v.x - f01.x, v.y - f01.y);
            __half2 l23 = __floats2half2_rn(v.z - f23.x, v.w - f23.y);
            uint2 hw, lw;
            hw.x = *(uint32_t*)&h01; hw.y = *(uint32_t*)&h23;
            lw.x = *(uint32_t*)&l01; lw.y = *(uint32_t*)&l23;
            *(uint2*)(Ash + r * STR + k4 * 2) = hw;
            *(uint2*)(Asl + r * STR + k4 * 2) = lw;
        }
        // ---- B chunk (pre-split): 128 rows x 32 half2-words -> 4 uint4 each
        #pragma unroll
        for (int i = 0; i < 4; i++) {
            int idx = t + i * 256;
            int r  = idx >> 3;
            int w4 = idx & 7;
            *(uint4*)(Bsh + r * STR + w4 * 4) =
                *(const uint4*)(Wh + (size_t)r * (DFEAT / 2) + kc * (KCH / 2) + w4 * 4);
            if (NPASS >= 3)
                *(uint4*)(Bsl + r * STR + w4 * 4) =
                    *(const uint4*)(Wl + (size_t)r * (DFEAT / 2) + kc * (KCH / 2) + w4 * 4);
        }
        __syncthreads();

        #pragma unroll
        for (int kk2 = 0; kk2 < KCH / 2; kk2 += 8) {   // one m16n8k16 per step
            uint32_t kb = (uint32_t)(kk2 * 4);         // byte offset for this step
            uint32_t ah[2][4], al[2][4];
            #pragma unroll
            for (int mt = 0; mt < 2; mt++) {
                LDSM_X4(ah[mt][0], ah[mt][1], ah[mt][2], ah[mt][3],
                        ash32 + aoffA[mt] + kb);
                LDSM_X4(al[mt][0], al[mt][1], al[mt][2], al[mt][3],
                        asl32 + aoffA[mt] + kb);
            }
            #pragma unroll
            for (int p = 0; p < WM; p++) {
                uint32_t pboff = aoffB + (uint32_t)(p * 16 * STR * 4);
                uint32_t bh0, bh1, bh2, bh3;
                LDSM_X4(bh0, bh1, bh2, bh3, bsh32 + pboff + kb);
                #pragma unroll
                for (int mt = 0; mt < 2; mt++) {
                    MMA_F16(acc[mt][2 * p],     ah[mt][0], ah[mt][1], ah[mt][2], ah[mt][3], bh0, bh1);
                    MMA_F16(acc[mt][2 * p],     al[mt][0], al[mt][1], al[mt][2], al[mt][3], bh0, bh1);
                    MMA_F16(acc[mt][2 * p + 1], ah[mt][0], ah[mt][1], ah[mt][2], ah[mt][3], bh2, bh3);
                    MMA_F16(acc[mt][2 * p + 1], al[mt][0], al[mt][1], al[mt][2], al[mt][3], bh2, bh3);
                }
                if (NPASS >= 3) {
                    uint32_t bl0, bl1, bl2, bl3;
                    LDSM_X4(bl0, bl1, bl2, bl3, bsl32 + pboff + kb);
                    #pragma unroll
                    for (int mt = 0; mt < 2; mt++) {
                        MMA_F16(acc[mt][2 * p],     ah[mt][0], ah[mt][1], ah[mt][2], ah[mt][3], bl0, bl1);
                        MMA_F16(acc[mt][2 * p + 1], ah[mt][0], ah[mt][1], ah[mt][2], ah[mt][3], bl2, bl3);
                    }
                }
            }
        }
        __syncthreads();
    }

    // ---- epilogue: bias + optional relu, write to C (row stride 2*OUTD)
    #pragma unroll
    for (int nt = 0; nt < NT; nt++) {
        int col = wn * (16 * WM) + nt * 8 + 2 * qi;
        float bx = bias[col], by = bias[col + 1];
        #pragma unroll
        for (int mt = 0; mt < 2; mt++) {
            int r0 = row0 + wm * 32 + mt * 16 + qp;
            float v0 = acc[mt][nt][0] + bx;
            float v1 = acc[mt][nt][1] + by;
            float v2 = acc[mt][nt][2] + bx;
            float v3 = acc[mt][nt][3] + by;
            if (do_relu) {
                v0 = fmaxf(v0, 0.f); v1 = fmaxf(v1, 0.f);
                v2 = fmaxf(v2, 0.f); v3 = fmaxf(v3, 0.f);
            }
            *(float2*)(C + (size_t)r0 * (2 * OUTD) + coloff + col)       = make_float2(v0, v1);
            *(float2*)(C + (size_t)(r0 + 8) * (2 * OUTD) + coloff + col) = make_float2(v2, v3);
        }
    }
}

// ---------------- host launcher ----------------
extern "C" void kernel_launch(void* const* d_in, const int* in_sizes, int n_in,
                              void* d_out, int out_size) {
    const int*   ids   = (const int*)d_in[0];
    const int*   adj   = (const int*)d_in[1];
    const float* feats = (const float*)d_in[2];
    const float* W1x   = (const float*)d_in[3];
    const float* b1x   = (const float*)d_in[4];
    const float* W1n   = (const float*)d_in[5];
    const float* b1n   = (const float*)d_in[6];
    const float* W2x   = (const float*)d_in[7];
    const float* b2x   = (const float*)d_in[8];
    const float* W2n   = (const float*)d_in[9];
    const float* b2n   = (const float*)d_in[10];
    float* out = (float*)d_out;

    float *p_m2, *p_z1, *p_m1, *p_z0, *p_m3;
    int *p_ids1, *p_ids2;
    cudaGetSymbolAddress((void**)&p_m2,  d_m2);
    cudaGetSymbolAddress((void**)&p_z1,  d_z1);
    cudaGetSymbolAddress((void**)&p_m1,  d_m1);
    cudaGetSymbolAddress((void**)&p_z0,  d_z0);
    cudaGetSymbolAddress((void**)&p_m3,  d_m3);
    cudaGetSymbolAddress((void**)&p_ids1, d_ids1);
    cudaGetSymbolAddress((void**)&p_ids2, d_ids2);

    // big kernel (NPASS=2): no Bsl buffer -> 2*64*36 + 128*36 = 9216 words
    const int SMEM_BIG   = (2 * 64 * STR + OUTD * STR) * 4;      // 36864 B
    const int SMEM_SMALL = (2 * 32 * STR + 2 * OUTD * STR) * 4;  // 46080 B
    cudaFuncSetAttribute(gemm_tc_kernel<1, 2, 2>,
                         cudaFuncAttributeMaxDynamicSharedMemorySize, SMEM_BIG);
    cudaFuncSetAttribute(gemm_tc_kernel<1, 1, 3>,
                         cudaFuncAttributeMaxDynamicSharedMemorySize, SMEM_SMALL);

    // 1. permutations (threefry, partitionable, bits1 ^ bits2)
    setup_perm_kernel<<<1, 128>>>();
    // 2. weight fp16 hi/lo split
    split_w_kernel<<<dim3(WSZH / 256, 4), 256>>>(W1x, W1n, W2x, W2n);
    // 3. neighbor id tables
    build_ids_kernel<<<(M1 + 255) / 256, 256>>>(ids, adj);
    // 4. m2 = mean_{fan2}(feats[ids2])   [25600,256]  — UNFUSED: full-chip
    //    parallel gather (6400 blocks) instead of serializing in 400 GEMM CTAs
    mean4_kernel<FAN2><<<M1 / 4, 256>>>(feats, p_ids2, p_m2);
    // 5. m1 = mean_{fan1}(feats[ids1])   [1024,256]
    mean4_kernel<FAN1><<<BATCH / 4, 256>>>(feats, p_ids1, p_m1);
    // 6. z1 = relu([feats[ids1]@W1x^T | m2@W1n^T] + b)   (plain A loads)
    gemm_tc_kernel<1, 2, 2><<<dim3(M1 / 64, 2), 256, SMEM_BIG>>>(
        feats, p_ids1, p_m2, nullptr, 0, 1, b1x, b1n, p_z1, 1);
    // 7. z0 = relu([feats[ids]@W1x^T | m1@W1n^T] + b)   (BM=32)
    gemm_tc_kernel<1, 1, 3><<<dim3(BATCH / 32, 2), 256, SMEM_SMALL>>>(
        feats, ids, p_m1, nullptr, 0, 1, b1x, b1n, p_z0, 1);
    // 8. m3 = mean_{fan1}(z1)   [1024,256]
    mean4_kernel<FAN1><<<BATCH / 4, 256>>>(p_z1, nullptr, p_m3);
    // 9. out = [z0@W2x^T + b2x | m3@W2n^T + b2n]   (no relu, BM=32)
    gemm_tc_kernel<1, 1, 3><<<dim3(BATCH / 32, 2), 256, SMEM_SMALL>>>(
        p_z0, nullptr, p_m3, nullptr, 2, 3, b2x, b2n, out, 0);
}

// round 12
// speedup vs baseline: 1.8646x; 1.0782x over previous
#include <cuda_runtime.h>
#include <cuda_fp16.h>
#include <cstdint>
#include <cstddef>

// ---------------- problem constants ----------------
#define NNODES   100000
#define DFEAT    256
#define MAXDEG   128
#define BATCH    1024
#define FAN1     25
#define FAN2     10
#define OUTD     128           // per-branch output
#define M1       (BATCH*FAN1)          // 25600
#define M2       (BATCH*FAN1*FAN2)     // 256000
#define WSZH     (OUTD * DFEAT / 2)    // half2 words per weight matrix = 16384
#define NB10     (M1 / 4)              // 6400 blocks for mean10
#define NB25     (BATCH / 4)           // 256 blocks for mean25

// ---------------- scratch (device globals; no allocation APIs) ----------------
__device__ int      d_cols1[FAN1];
__device__ int      d_cols2[FAN2];
__device__ int      d_ids1[M1];
__device__ int      d_ids2[M2];
__device__ float    d_m2[M1 * DFEAT];     // mean over fan2 of feats[ids2]
__device__ float    d_z1[M1 * DFEAT];     // layer-1 output for ids1 rows
__device__ float    d_m1[BATCH * DFEAT];  // mean over fan1 of feats[ids1]
__device__ float    d_z0[BATCH * DFEAT];  // layer-1 output for ids rows
__device__ float    d_m3[BATCH * DFEAT];  // mean over fan1 of z1
__device__ uint32_t d_Whh[4 * WSZH];      // fp16 hi of weights, [n][k] half2-packed
__device__ uint32_t d_Wll[4 * WSZH];      // fp16 lo

// ---------------- threefry2x32 (JAX-exact, 20 rounds) ----------------
__device__ __forceinline__ uint32_t rotl32(uint32_t v, int r) {
    return (v << r) | (v >> (32 - r));
}

__device__ __forceinline__ void tf2x32(uint32_t k0, uint32_t k1,
                                       uint32_t x0, uint32_t x1,
                                       uint32_t& y0, uint32_t& y1) {
    uint32_t ks0 = k0, ks1 = k1, ks2 = k0 ^ k1 ^ 0x1BD11BDAu;
    x0 += ks0; x1 += ks1;
    const int r0[4] = {13, 15, 26, 6};
    const int r1[4] = {17, 29, 16, 24};
#define TF_G(RR) { x0 += x1; x1 = rotl32(x1, RR[0]); x1 ^= x0; \
                   x0 += x1; x1 = rotl32(x1, RR[1]); x1 ^= x0; \
                   x0 += x1; x1 = rotl32(x1, RR[2]); x1 ^= x0; \
                   x0 += x1; x1 = rotl32(x1, RR[3]); x1 ^= x0; }
    TF_G(r0); x0 += ks1; x1 += ks2 + 1u;
    TF_G(r1); x0 += ks2; x1 += ks0 + 2u;
    TF_G(r0); x0 += ks0; x1 += ks1 + 3u;
    TF_G(r1); x0 += ks1; x1 += ks2 + 4u;
    TF_G(r0); x0 += ks2; x1 += ks0 + 5u;
#undef TF_G
    y0 = x0; y1 = x1;
}

// jax.random.permutation(k, 128) for k1,k2 = split(key(42)),
// partitionable semantics; random_bits(32) = bits1 ^ bits2 (VERIFIED round 4)
__global__ void setup_perm_kernel() {
    int t = threadIdx.x;  // 128 threads
    uint32_t k1a, k1b, k2a, k2b;
    tf2x32(0u, 42u, 0u, 0u, k1a, k1b);
    tf2x32(0u, 42u, 0u, 1u, k2a, k2b);
    uint32_t s1a, s1b, s2a, s2b;
    tf2x32(k1a, k1b, 0u, 1u, s1a, s1b);
    tf2x32(k2a, k2b, 0u, 1u, s2a, s2b);

    __shared__ uint32_t keys[MAXDEG];
    uint32_t b1, b2;

    tf2x32(s1a, s1b, 0u, (uint32_t)t, b1, b2);
    keys[t] = b1 ^ b2;
    __syncthreads();
    {
        uint32_t me = keys[t];
        int rank = 0;
        #pragma unroll 8
        for (int j = 0; j < MAXDEG; j++) {
            uint32_t kj = keys[j];
            rank += (kj < me) || (kj == me && j < t);
        }
        if (rank < FAN1) d_cols1[rank] = t;
    }
    __syncthreads();

    tf2x32(s2a, s2b, 0u, (uint32_t)t, b1, b2);
    keys[t] = b1 ^ b2;
    __syncthreads();
    {
        uint32_t me = keys[t];
        int rank = 0;
        #pragma unroll 8
        for (int j = 0; j < MAXDEG; j++) {
            uint32_t kj = keys[j];
            rank += (kj < me) || (kj == me && j < t);
        }
        if (rank < FAN2) d_cols2[rank] = t;
    }
}

// Build ids1[B*25] and ids2[B*250]
__global__ void build_ids_kernel(const int* __restrict__ ids,
                                 const int* __restrict__ adj) {
    int i = blockIdx.x * blockDim.x + threadIdx.x;
    if (i >= M1) return;
    int b = i / FAN1, s = i - b * FAN1;
    int id0 = ids[b];
    int id1 = adj[(size_t)id0 * MAXDEG + d_cols1[s]];
    d_ids1[i] = id1;
    const int* arow = adj + (size_t)id1 * MAXDEG;
    #pragma unroll
    for (int j = 0; j < FAN2; j++) {
        d_ids2[(size_t)i * FAN2 + j] = arow[d_cols2[j]];
    }
}

// mean over NS rows of src, 4 rows per block, float4 lanes, ILP-4 accumulators
template <int NS>
__device__ __forceinline__ void mean_body(const float* __restrict__ src,
                                          const int* __restrict__ idx,
                                          float* __restrict__ out, int blk) {
    __shared__ int sidx[4][NS];
    int t = threadIdx.x;
    int row0 = blk * 4;
    if (t < 4 * NS) {
        int rr = t / NS, jj = t - rr * NS;
        sidx[rr][jj] = idx ? idx[(size_t)(row0 + rr) * NS + jj]
                           : (row0 + rr) * NS + jj;
    }
    __syncthreads();
    int rr = t >> 6;
    int c4 = (t & 63) * 4;
    float4 a0 = make_float4(0.f, 0.f, 0.f, 0.f), a1 = a0, a2 = a0, a3 = a0;
    int j = 0;
    #pragma unroll
    for (; j + 4 <= NS; j += 4) {
        const float4 v0 = *(const float4*)(src + (size_t)sidx[rr][j + 0] * DFEAT + c4);
        const float4 v1 = *(const float4*)(src + (size_t)sidx[rr][j + 1] * DFEAT + c4);
        const float4 v2 = *(const float4*)(src + (size_t)sidx[rr][j + 2] * DFEAT + c4);
        const float4 v3 = *(const float4*)(src + (size_t)sidx[rr][j + 3] * DFEAT + c4);
        a0.x += v0.x; a0.y += v0.y; a0.z += v0.z; a0.w += v0.w;
        a1.x += v1.x; a1.y += v1.y; a1.z += v1.z; a1.w += v1.w;
        a2.x += v2.x; a2.y += v2.y; a2.z += v2.z; a2.w += v2.w;
        a3.x += v3.x; a3.y += v3.y; a3.z += v3.z; a3.w += v3.w;
    }
    #pragma unroll
    for (; j < NS; j++) {
        const float4 v0 = *(const float4*)(src + (size_t)sidx[rr][j] * DFEAT + c4);
        a0.x += v0.x; a0.y += v0.y; a0.z += v0.z; a0.w += v0.w;
    }
    const float inv = 1.0f / NS;
    float4 s;
    s.x = (a0.x + a1.x + a2.x + a3.x) * inv;
    s.y = (a0.y + a1.y + a2.y + a3.y) * inv;
    s.z = (a0.z + a1.z + a2.z + a3.z) * inv;
    s.w = (a0.w + a1.w + a2.w + a3.w) * inv;
    *(float4*)(out + (size_t)(row0 + rr) * DFEAT + c4) = s;
}

// merged: mean10(feats[ids2])->m2  (blocks [0,NB10))  and
//         mean25(feats[ids1])->m1  (blocks [NB10,NB10+NB25))
__global__ __launch_bounds__(256)
void means_kernel(const float* __restrict__ feats) {
    if (blockIdx.x < NB10)
        mean_body<FAN2>(feats, d_ids2, d_m2, blockIdx.x);
    else
        mean_body<FAN1>(feats, d_ids1, d_m1, blockIdx.x - NB10);
}

// standalone mean25 of contiguous z1 groups -> m3
__global__ __launch_bounds__(256)
void mean_m3_kernel(const float* __restrict__ z1) {
    mean_body<FAN1>(z1, nullptr, d_m3, blockIdx.x);
}

// one-shot fp16 hi/lo split of the 4 weight matrices, [n][k] half2-packed
__global__ void split_w_kernel(const float* __restrict__ W1x,
                               const float* __restrict__ W1n,
                               const float* __restrict__ W2x,
                               const float* __restrict__ W2n) {
    int m = blockIdx.y;
    const float* W = (m == 0) ? W1x : (m == 1) ? W1n : (m == 2) ? W2x : W2n;
    int i = blockIdx.x * blockDim.x + threadIdx.x;   // half2-pair index
    if (i < WSZH) {
        float w0 = W[2 * i], w1 = W[2 * i + 1];
        __half h0 = __float2half_rn(w0), h1 = __float2half_rn(w1);
        float l0 = w0 - __half2float(h0);
        float l1 = w1 - __half2float(h1);
        __half2 hh = __halves2half2(h0, h1);
        __half2 ll = __floats2half2_rn(l0, l1);
        d_Whh[(size_t)m * WSZH + i] = *(uint32_t*)&hh;
        d_Wll[(size_t)m * WSZH + i] = *(uint32_t*)&ll;
    }
}

#define MMA_F16(d, a0, a1, a2, a3, b0, b1) \
    asm volatile( \
        "mma.sync.aligned.m16n8k16.row.col.f32.f16.f16.f32 " \
        "{%0,%1,%2,%3}, {%4,%5,%6,%7}, {%8,%9}, {%0,%1,%2,%3};" \
        : "+f"((d)[0]), "+f"((d)[1]), "+f"((d)[2]), "+f"((d)[3]) \
        : "r"(a0), "r"(a1), "r"(a2), "r"(a3), "r"(b0), "r"(b1))

#define LDSM_X4(r0, r1, r2, r3, addr) \
    asm volatile( \
        "ldmatrix.sync.aligned.m8n8.x4.shared.b16 {%0,%1,%2,%3}, [%4];" \
        : "=r"(r0), "=r"(r1), "=r"(r2), "=r"(r3) : "r"(addr))

// ---------------- tensor-core segmented dual-branch GEMM (fp16 split) --------
// gridDim.y = 2 selects branch (x-branch gathered A | n-branch contiguous A);
// blockIdx.x < NB0 -> segment a (rows of C0), else segment b (rows of C1).
// Both segments share weights/biases (same layer). Fragments via ldmatrix.
// Template: WM = warps in M (BM = 32*WM); NPASS = 2 (A-compensated) or 3.
// smem half2-words, row stride 36 (== 4 mod 32: conflict-free LDSM phases).
#define KCH   64
#define STR   36

template <int WM, int NPASS>
__global__ __launch_bounds__(256, (NPASS == 2 ? 4 : 3))
void gemm_tc_kernel(const float* __restrict__ A0a, const int* __restrict__ g0a,
                    const float* __restrict__ A1a, float* __restrict__ C0, int NB0,
                    const float* __restrict__ A0b, const int* __restrict__ g0b,
                    const float* __restrict__ A1b, float* __restrict__ C1,
                    int wsel0, int wsel1,
                    const float* __restrict__ bias0, const float* __restrict__ bias1,
                    int do_relu) {
    constexpr int BM = 32 * WM;
    extern __shared__ uint32_t smx[];
    uint32_t* Ash = smx;
    uint32_t* Asl = smx + BM * STR;
    uint32_t* Bsh = smx + 2 * BM * STR;
    uint32_t* Bsl = smx + 2 * BM * STR + OUTD * STR;   // only valid if NPASS>=3
    __shared__ int rowidx[BM];

    int bx = blockIdx.x;
    const float* A0; const int* g0; const float* A1; float* C; int rowblk;
    if (bx < NB0) { A0 = A0a; g0 = g0a; A1 = A1a; C = C0; rowblk = bx; }
    else          { A0 = A0b; g0 = g0b; A1 = A1b; C = C1; rowblk = bx - NB0; }

    int branch = blockIdx.y;
    const float* Asrc = branch ? A1 : A0;
    const int*   gidx = branch ? nullptr : g0;   // n-branch is always contiguous
    const uint32_t* Wh = d_Whh + (size_t)(branch ? wsel1 : wsel0) * WSZH;
    const uint32_t* Wl = d_Wll + (size_t)(branch ? wsel1 : wsel0) * WSZH;
    const float* bias = branch ? bias1 : bias0;
    int coloff = branch * OUTD;

    int t = threadIdx.x;
    int row0 = rowblk * BM;
    if (t < BM) rowidx[t] = gidx ? gidx[row0 + t] : (row0 + t);
    __syncthreads();

    int wid = t >> 5, lane = t & 31;
    int wm = wid % WM;              // M slab (32 rows per warp)
    int wn = wid / WM;              // N slab (16*WM cols per warp)
    int qp = lane >> 2;             // 0..7 (epilogue)
    int qi = lane & 3;              // 0..3 (epilogue)
    constexpr int NT = 2 * WM;      // 8-col tiles per warp

    // ---- ldmatrix base addresses (bytes; constant across k-chunks) ----
    uint32_t ash32 = (uint32_t)__cvta_generic_to_shared(Ash);
    uint32_t asl32 = (uint32_t)__cvta_generic_to_shared(Asl);
    uint32_t bsh32 = (uint32_t)__cvta_generic_to_shared(Bsh);
    uint32_t bsl32 = (uint32_t)__cvta_generic_to_shared(Bsl);
    uint32_t aoffA[2], aoffB;
    #pragma unroll
    for (int mt = 0; mt < 2; mt++)
        aoffA[mt] = (uint32_t)(((wm * 32 + mt * 16 + (lane & 15)) * STR
                                + (lane >> 4) * 4) * 4);
    aoffB = (uint32_t)(((wn * (16 * WM) + (lane >> 4) * 8 + (lane & 7)) * STR
                        + ((lane >> 3) & 1) * 4) * 4);

    float acc[2][NT][4];
    #pragma unroll
    for (int mt = 0; mt < 2; mt++)
        #pragma unroll
        for (int nt = 0; nt < NT; nt++)
            #pragma unroll
            for (int j = 0; j < 4; j++) acc[mt][nt][j] = 0.f;

    for (int kc = 0; kc < 4; kc++) {
        // ---- A chunk: BM rows x 64 k = BM*16 float4 / 256 thr
        #pragma unroll
        for (int i = 0; i < 2 * WM; i++) {
            int idx = t + i * 256;
            int r  = idx >> 4;
            int k4 = idx & 15;
            const float4 v = *(const float4*)(Asrc + (size_t)rowidx[r] * DFEAT
                                              + kc * KCH + k4 * 4);
            __half2 h01 = __floats2half2_rn(v.x, v.y);
            __half2 h23 = __floats2half2_rn(v.z, v.w);
            float2 f01 = __half22float2(h01);
            float2 f23 = __half22float2(h23);
            __half2 l01 = __floats2half2_rn(v.x - f01.x, v.y - f01.y);
            __half2 l23 = __floats2half2_rn(v.z - f23.x, v.w - f23.y);
            uint2 hw, lw;
            hw.x = *(uint32_t*)&h01; hw.y = *(uint32_t*)&h23;
            lw.x = *(uint32_t*)&l01; lw.y = *(uint32_t*)&l23;
            *(uint2*)(Ash + r * STR + k4 * 2) = hw;
            *(uint2*)(Asl + r * STR + k4 * 2) = lw;
        }
        // ---- B chunk (pre-split): 128 rows x 32 half2-words -> 4 uint4 each
        #pragma unroll
        for (int i = 0; i < 4; i++) {
            int idx = t + i * 256;
            int r  = idx >> 3;
            int w4 = idx & 7;
            *(uint4*)(Bsh + r * STR + w4 * 4) =
                *(const uint4*)(Wh + (size_t)r * (DFEAT / 2) + kc * (KCH / 2) + w4 * 4);
            if (NPASS >= 3)
                *(uint4*)(Bsl + r * STR + w4 * 4) =
                    *(const uint4*)(Wl + (size_t)r * (DFEAT / 2) + kc * (KCH / 2) + w4 * 4);
        }
        __syncthreads();

        #pragma unroll
        for (int kk2 = 0; kk2 < KCH / 2; kk2 += 8) {   // one m16n8k16 per step
            uint32_t kb = (uint32_t)(kk2 * 4);
            uint32_t ah[2][4], al[2][4];
            #pragma unroll
            for (int mt = 0; mt < 2; mt++) {
                LDSM_X4(ah[mt][0], ah[mt][1], ah[mt][2], ah[mt][3],
                        ash32 + aoffA[mt] + kb);
                LDSM_X4(al[mt][0], al[mt][1], al[mt][2], al[mt][3],
                        asl32 + aoffA[mt] + kb);
            }
            #pragma unroll
            for (int p = 0; p < WM; p++) {
                uint32_t pboff = aoffB + (uint32_t)(p * 16 * STR * 4);
                uint32_t bh0, bh1, bh2, bh3;
                LDSM_X4(bh0, bh1, bh2, bh3, bsh32 + pboff + kb);
                #pragma unroll
                for (int mt = 0; mt < 2; mt++) {
                    MMA_F16(acc[mt][2 * p],     ah[mt][0], ah[mt][1], ah[mt][2], ah[mt][3], bh0, bh1);
                    MMA_F16(acc[mt][2 * p],     al[mt][0], al[mt][1], al[mt][2], al[mt][3], bh0, bh1);
                    MMA_F16(acc[mt][2 * p + 1], ah[mt][0], ah[mt][1], ah[mt][2], ah[mt][3], bh2, bh3);
                    MMA_F16(acc[mt][2 * p + 1], al[mt][0], al[mt][1], al[mt][2], al[mt][3], bh2, bh3);
                }
                if (NPASS >= 3) {
                    uint32_t bl0, bl1, bl2, bl3;
                    LDSM_X4(bl0, bl1, bl2, bl3, bsl32 + pboff + kb);
                    #pragma unroll
                    for (int mt = 0; mt < 2; mt++) {
                        MMA_F16(acc[mt][2 * p],     ah[mt][0], ah[mt][1], ah[mt][2], ah[mt][3], bl0, bl1);
                        MMA_F16(acc[mt][2 * p + 1], ah[mt][0], ah[mt][1], ah[mt][2], ah[mt][3], bl2, bl3);
                    }
                }
            }
        }
        __syncthreads();
    }

    // ---- epilogue: bias + optional relu, write to C (row stride 2*OUTD)
    #pragma unroll
    for (int nt = 0; nt < NT; nt++) {
        int col = wn * (16 * WM) + nt * 8 + 2 * qi;
        float bx2 = bias[col], by = bias[col + 1];
        #pragma unroll
        for (int mt = 0; mt < 2; mt++) {
            int r0 = row0 + wm * 32 + mt * 16 + qp;
            float v0 = acc[mt][nt][0] + bx2;
            float v1 = acc[mt][nt][1] + by;
            float v2 = acc[mt][nt][2] + bx2;
            float v3 = acc[mt][nt][3] + by;
            if (do_relu) {
                v0 = fmaxf(v0, 0.f); v1 = fmaxf(v1, 0.f);
                v2 = fmaxf(v2, 0.f); v3 = fmaxf(v3, 0.f);
            }
            *(float2*)(C + (size_t)r0 * (2 * OUTD) + coloff + col)       = make_float2(v0, v1);
            *(float2*)(C + (size_t)(r0 + 8) * (2 * OUTD) + coloff + col) = make_float2(v2, v3);
        }
    }
}

// ---------------- host launcher ----------------
extern "C" void kernel_launch(void* const* d_in, const int* in_sizes, int n_in,
                              void* d_out, int out_size) {
    const int*   ids   = (const int*)d_in[0];
    const int*   adj   = (const int*)d_in[1];
    const float* feats = (const float*)d_in[2];
    const float* W1x   = (const float*)d_in[3];
    const float* b1x   = (const float*)d_in[4];
    const float* W1n   = (const float*)d_in[5];
    const float* b1n   = (const float*)d_in[6];
    const float* W2x   = (const float*)d_in[7];
    const float* b2x   = (const float*)d_in[8];
    const float* W2n   = (const float*)d_in[9];
    const float* b2n   = (const float*)d_in[10];
    float* out = (float*)d_out;

    float *p_m2, *p_z1, *p_m1, *p_z0, *p_m3;
    int *p_ids1;
    cudaGetSymbolAddress((void**)&p_m2,  d_m2);
    cudaGetSymbolAddress((void**)&p_z1,  d_z1);
    cudaGetSymbolAddress((void**)&p_m1,  d_m1);
    cudaGetSymbolAddress((void**)&p_z0,  d_z0);
    cudaGetSymbolAddress((void**)&p_m3,  d_m3);
    cudaGetSymbolAddress((void**)&p_ids1, d_ids1);

    // layer-1 (NPASS=2): no Bsl buffer -> 2*64*36 + 128*36 = 9216 words
    const int SMEM_L1  = (2 * 64 * STR + OUTD * STR) * 4;      // 36864 B
    const int SMEM_OUT = (2 * 32 * STR + 2 * OUTD * STR) * 4;  // 46080 B
    cudaFuncSetAttribute(gemm_tc_kernel<2, 2>,
                         cudaFuncAttributeMaxDynamicSharedMemorySize, SMEM_L1);
    cudaFuncSetAttribute(gemm_tc_kernel<1, 3>,
                         cudaFuncAttributeMaxDynamicSharedMemorySize, SMEM_OUT);

    // 1. permutations (threefry, partitionable, bits1 ^ bits2)
    setup_perm_kernel<<<1, 128>>>();
    // 2. weight fp16 hi/lo split
    split_w_kernel<<<dim3(WSZH / 256, 4), 256>>>(W1x, W1n, W2x, W2n);
    // 3. neighbor id tables
    build_ids_kernel<<<(M1 + 255) / 256, 256>>>(ids, adj);
    // 4. MERGED means: m2 = mean10(feats[ids2]) [6400 blk] + m1 = mean25(feats[ids1]) [256 blk]
    means_kernel<<<NB10 + NB25, 256>>>(feats);
    // 5. MERGED layer-1 GEMM: seg a (400 CTAs) -> z1 rows; seg b (16 CTAs) -> z0 rows
    //    z1 = relu([feats[ids1]@W1x | m2@W1n] + b); z0 = relu([feats[ids]@W1x | m1@W1n] + b)
    gemm_tc_kernel<2, 2><<<dim3(M1 / 64 + BATCH / 64, 2), 256, SMEM_L1>>>(
        feats, p_ids1, p_m2, p_z1, M1 / 64,
        feats, ids,    p_m1, p_z0,
        0, 1, b1x, b1n, 1);
    // 6. m3 = mean25(z1 contiguous groups)
    mean_m3_kernel<<<NB25, 256>>>(p_z1);
    // 7. out = [z0@W2x + b2x | m3@W2n + b2n]  (no relu, BM=32, 3-pass)
    gemm_tc_kernel<1, 3><<<dim3(BATCH / 32, 2), 256, SMEM_OUT>>>(
        p_z0, nullptr, p_m3, out, BATCH / 32,
        p_z0, nullptr, p_m3, out,
        2, 3, b2x, b2n, 0);
}

// round 14
// speedup vs baseline: 1.9155x; 1.0273x over previous
#include <cuda_runtime.h>
#include <cuda_fp16.h>
#include <cstdint>
#include <cstddef>

// ---------------- problem constants ----------------
#define NNODES   100000
#define DFEAT    256
#define MAXDEG   128
#define BATCH    1024
#define FAN1     25
#define FAN2     10
#define OUTD     128           // per-branch output
#define M1       (BATCH*FAN1)          // 25600
#define M2       (BATCH*FAN1*FAN2)     // 256000
#define WSZH     (OUTD * DFEAT / 2)    // half2 words per weight matrix = 16384
#define NB10     (M1 / 4)              // 6400 blocks for mean10
#define NB25     (BATCH / 4)           // 256 blocks for mean25
#define NBG_Z1   (M1 / 64)             // 400 GEMM tiles for z1
#define NBG_Z0   (BATCH / 64)          // 16 GEMM tiles for z0

// ---------------- scratch (device globals; no allocation APIs) ----------------
__device__ int      d_cols1[FAN1];
__device__ int      d_cols2[FAN2];
__device__ int      d_ids1[M1];
__device__ int      d_ids2[M2];
__device__ float    d_m2[M1 * DFEAT];     // mean over fan2 of feats[ids2]
__device__ float    d_z1[M1 * DFEAT];     // layer-1 output for ids1 rows
__device__ float    d_m1[BATCH * DFEAT];  // mean over fan1 of feats[ids1]
__device__ float    d_z0[BATCH * DFEAT];  // layer-1 output for ids rows
__device__ float    d_m3[BATCH * DFEAT];  // mean over fan1 of z1
__device__ uint32_t d_Whh[4 * WSZH];      // fp16 hi of weights, [n][k] half2-packed
__device__ uint32_t d_Wll[4 * WSZH];      // fp16 lo

// ---------------- threefry2x32 (JAX-exact, 20 rounds) ----------------
__device__ __forceinline__ uint32_t rotl32(uint32_t v, int r) {
    return (v << r) | (v >> (32 - r));
}

__device__ __forceinline__ void tf2x32(uint32_t k0, uint32_t k1,
                                       uint32_t x0, uint32_t x1,
                                       uint32_t& y0, uint32_t& y1) {
    uint32_t ks0 = k0, ks1 = k1, ks2 = k0 ^ k1 ^ 0x1BD11BDAu;
    x0 += ks0; x1 += ks1;
    const int r0[4] = {13, 15, 26, 6};
    const int r1[4] = {17, 29, 16, 24};
#define TF_G(RR) { x0 += x1; x1 = rotl32(x1, RR[0]); x1 ^= x0; \
                   x0 += x1; x1 = rotl32(x1, RR[1]); x1 ^= x0; \
                   x0 += x1; x1 = rotl32(x1, RR[2]); x1 ^= x0; \
                   x0 += x1; x1 = rotl32(x1, RR[3]); x1 ^= x0; }
    TF_G(r0); x0 += ks1; x1 += ks2 + 1u;
    TF_G(r1); x0 += ks2; x1 += ks0 + 2u;
    TF_G(r0); x0 += ks0; x1 += ks1 + 3u;
    TF_G(r1); x0 += ks1; x1 += ks2 + 4u;
    TF_G(r0); x0 += ks2; x1 += ks0 + 5u;
#undef TF_G
    y0 = x0; y1 = x1;
}

// jax.random.permutation(k, 128) for k1,k2 = split(key(42)),
// partitionable semantics; random_bits(32) = bits1 ^ bits2 (VERIFIED round 4)
__global__ void setup_perm_kernel() {
    int t = threadIdx.x;  // 128 threads
    uint32_t k1a, k1b, k2a, k2b;
    tf2x32(0u, 42u, 0u, 0u, k1a, k1b);
    tf2x32(0u, 42u, 0u, 1u, k2a, k2b);
    uint32_t s1a, s1b, s2a, s2b;
    tf2x32(k1a, k1b, 0u, 1u, s1a, s1b);
    tf2x32(k2a, k2b, 0u, 1u, s2a, s2b);

    __shared__ uint32_t keys[MAXDEG];
    uint32_t b1, b2;

    tf2x32(s1a, s1b, 0u, (uint32_t)t, b1, b2);
    keys[t] = b1 ^ b2;
    __syncthreads();
    {
        uint32_t me = keys[t];
        int rank = 0;
        #pragma unroll 8
        for (int j = 0; j < MAXDEG; j++) {
            uint32_t kj = keys[j];
            rank += (kj < me) || (kj == me && j < t);
        }
        if (rank < FAN1) d_cols1[rank] = t;
    }
    __syncthreads();

    tf2x32(s2a, s2b, 0u, (uint32_t)t, b1, b2);
    keys[t] = b1 ^ b2;
    __syncthreads();
    {
        uint32_t me = keys[t];
        int rank = 0;
        #pragma unroll 8
        for (int j = 0; j < MAXDEG; j++) {
            uint32_t kj = keys[j];
            rank += (kj < me) || (kj == me && j < t);
        }
        if (rank < FAN2) d_cols2[rank] = t;
    }
}

// Build ids1[B*25] and ids2[B*250]
__global__ void build_ids_kernel(const int* __restrict__ ids,
                                 const int* __restrict__ adj) {
    int i = blockIdx.x * blockDim.x + threadIdx.x;
    if (i >= M1) return;
    int b = i / FAN1, s = i - b * FAN1;
    int id0 = ids[b];
    int id1 = adj[(size_t)id0 * MAXDEG + d_cols1[s]];
    d_ids1[i] = id1;
    const int* arow = adj + (size_t)id1 * MAXDEG;
    #pragma unroll
    for (int j = 0; j < FAN2; j++) {
        d_ids2[(size_t)i * FAN2 + j] = arow[d_cols2[j]];
    }
}

// mean over NS rows of src, 4 rows per block, float4 lanes, ILP-4 accumulators
template <int NS>
__device__ __forceinline__ void mean_body(const float* __restrict__ src,
                                          const int* __restrict__ idx,
                                          float* __restrict__ out, int blk) {
    __shared__ int sidx[4][NS];
    int t = threadIdx.x;
    int row0 = blk * 4;
    if (t < 4 * NS) {
        int rr = t / NS, jj = t - rr * NS;
        sidx[rr][jj] = idx ? idx[(size_t)(row0 + rr) * NS + jj]
                           : (row0 + rr) * NS + jj;
    }
    __syncthreads();
    int rr = t >> 6;
    int c4 = (t & 63) * 4;
    float4 a0 = make_float4(0.f, 0.f, 0.f, 0.f), a1 = a0, a2 = a0, a3 = a0;
    int j = 0;
    #pragma unroll
    for (; j + 4 <= NS; j += 4) {
        const float4 v0 = *(const float4*)(src + (size_t)sidx[rr][j + 0] * DFEAT + c4);
        const float4 v1 = *(const float4*)(src + (size_t)sidx[rr][j + 1] * DFEAT + c4);
        const float4 v2 = *(const float4*)(src + (size_t)sidx[rr][j + 2] * DFEAT + c4);
        const float4 v3 = *(const float4*)(src + (size_t)sidx[rr][j + 3] * DFEAT + c4);
        a0.x += v0.x; a0.y += v0.y; a0.z += v0.z; a0.w += v0.w;
        a1.x += v1.x; a1.y += v1.y; a1.z += v1.z; a1.w += v1.w;
        a2.x += v2.x; a2.y += v2.y; a2.z += v2.z; a2.w += v2.w;
        a3.x += v3.x; a3.y += v3.y; a3.z += v3.z; a3.w += v3.w;
    }
    #pragma unroll
    for (; j < NS; j++) {
        const float4 v0 = *(const float4*)(src + (size_t)sidx[rr][j] * DFEAT + c4);
        a0.x += v0.x; a0.y += v0.y; a0.z += v0.z; a0.w += v0.w;
    }
    const float inv = 1.0f / NS;
    float4 s;
    s.x = (a0.x + a1.x + a2.x + a3.x) * inv;
    s.y = (a0.y + a1.y + a2.y + a3.y) * inv;
    s.z = (a0.z + a1.z + a2.z + a3.z) * inv;
    s.w = (a0.w + a1.w + a2.w + a3.w) * inv;
    *(float4*)(out + (size_t)(row0 + rr) * DFEAT + c4) = s;
}

// standalone mean25 of contiguous z1 groups -> m3
__global__ __launch_bounds__(256)
void mean_m3_kernel(const float* __restrict__ z1) {
    mean_body<FAN1>(z1, nullptr, d_m3, blockIdx.x);
}

// one-shot fp16 hi/lo split of the 4 weight matrices, [n][k] half2-packed
__global__ void split_w_kernel(const float* __restrict__ W1x,
                               const float* __restrict__ W1n,
                               const float* __restrict__ W2x,
                               const float* __restrict__ W2n) {
    int m = blockIdx.y;
    const float* W = (m == 0) ? W1x : (m == 1) ? W1n : (m == 2) ? W2x : W2n;
    int i = blockIdx.x * blockDim.x + threadIdx.x;   // half2-pair index
    if (i < WSZH) {
        float w0 = W[2 * i], w1 = W[2 * i + 1];
        __half h0 = __float2half_rn(w0), h1 = __float2half_rn(w1);
        float l0 = w0 - __half2float(h0);
        float l1 = w1 - __half2float(h1);
        __half2 hh = __halves2half2(h0, h1);
        __half2 ll = __floats2half2_rn(l0, l1);
        d_Whh[(size_t)m * WSZH + i] = *(uint32_t*)&hh;
        d_Wll[(size_t)m * WSZH + i] = *(uint32_t*)&ll;
    }
}

#define MMA_F16(d, a0, a1, a2, a3, b0, b1) \
    asm volatile( \
        "mma.sync.aligned.m16n8k16.row.col.f32.f16.f16.f32 " \
        "{%0,%1,%2,%3}, {%4,%5,%6,%7}, {%8,%9}, {%0,%1,%2,%3};" \
        : "+f"((d)[0]), "+f"((d)[1]), "+f"((d)[2]), "+f"((d)[3]) \
        : "r"(a0), "r"(a1), "r"(a2), "r"(a3), "r"(b0), "r"(b1))

#define LDSM_X4(r0, r1, r2, r3, addr) \
    asm volatile( \
        "ldmatrix.sync.aligned.m8n8.x4.shared.b16 {%0,%1,%2,%3}, [%4];" \
        : "=r"(r0), "=r"(r1), "=r"(r2), "=r"(r3) : "r"(addr))

// ---------------- GEMM tile device function (fp16 split, LDSM) ---------------
// C[row, coloff+c] = act( A[row,:] @ W[c,:] + bias[c] ) for a BM x 128 tile.
// A fp32 gathered via gidx (or contiguous). Wh/Wl pre-split fp16 [n][k].
// NPASS = 2 (A-compensated) or 3 (A- and B-compensated).
// smem half2-words, row stride 36 (== 4 mod 32: conflict-free LDSM phases).
#define KCH   64
#define STR   36

template <int WM, int NPASS>
__device__ __forceinline__ void gemm_tile(
    const float* __restrict__ Asrc, const int* __restrict__ gidx,
    const uint32_t* __restrict__ Wh, const uint32_t* __restrict__ Wl,
    const float* __restrict__ bias, float* __restrict__ C,
    int row0, int coloff, int do_relu, uint32_t* smx) {
    constexpr int BM = 32 * WM;
    uint32_t* Ash = smx;
    uint32_t* Asl = smx + BM * STR;
    uint32_t* Bsh = smx + 2 * BM * STR;
    uint32_t* Bsl = smx + 2 * BM * STR + OUTD * STR;   // only valid if NPASS>=3
    __shared__ int rowidx[64];

    int t = threadIdx.x;
    if (t < BM) rowidx[t] = gidx ? gidx[row0 + t] : (row0 + t);
    __syncthreads();

    int wid = t >> 5, lane = t & 31;
    int wm = wid % WM;
    int wn = wid / WM;
    int qp = lane >> 2;
    int qi = lane & 3;
    constexpr int NT = 2 * WM;

    uint32_t ash32 = (uint32_t)__cvta_generic_to_shared(Ash);
    uint32_t asl32 = (uint32_t)__cvta_generic_to_shared(Asl);
    uint32_t bsh32 = (uint32_t)__cvta_generic_to_shared(Bsh);
    uint32_t bsl32 = (uint32_t)__cvta_generic_to_shared(Bsl);
    uint32_t aoffA[2], aoffB;
    #pragma unroll
    for (int mt = 0; mt < 2; mt++)
        aoffA[mt] = (uint32_t)(((wm * 32 + mt * 16 + (lane & 15)) * STR
                                + (lane >> 4) * 4) * 4);
    aoffB = (uint32_t)(((wn * (16 * WM) + (lane >> 4) * 8 + (lane & 7)) * STR
                        + ((lane >> 3) & 1) * 4) * 4);

    float acc[2][NT][4];
    #pragma unroll
    for (int mt = 0; mt < 2; mt++)
        #pragma unroll
        for (int nt = 0; nt < NT; nt++)
            #pragma unroll
            for (int j = 0; j < 4; j++) acc[mt][nt][j] = 0.f;

    for (int kc = 0; kc < 4; kc++) {
        #pragma unroll
        for (int i = 0; i < 2 * WM; i++) {
            int idx = t + i * 256;
            int r  = idx >> 4;
            int k4 = idx & 15;
            const float4 v = *(const float4*)(Asrc + (size_t)rowidx[r] * DFEAT
                                              + kc * KCH + k4 * 4);
            __half2 h01 = __floats2half2_rn(v.x, v.y);
            __half2 h23 = __floats2half2_rn(v.z, v.w);
            float2 f01 = __half22float2(h01);
            float2 f23 = __half22float2(h23);
            __half2 l01 = __floats2half2_rn(v.x - f01.x, v.y - f01.y);
            __half2 l23 = __floats2half2_rn(v.z - f23.x, v.w - f23.y);
            uint2 hw, lw;
            hw.x = *(uint32_t*)&h01; hw.y = *(uint32_t*)&h23;
            lw.x = *(uint32_t*)&l01; lw.y = *(uint32_t*)&l23;
            *(uint2*)(Ash + r * STR + k4 * 2) = hw;
            *(uint2*)(Asl + r * STR + k4 * 2) = lw;
        }
        #pragma unroll
        for (int i = 0; i < 4; i++) {
            int idx = t + i * 256;
            int r  = idx >> 3;
            int w4 = idx & 7;
            *(uint4*)(Bsh + r * STR + w4 * 4) =
                *(const uint4*)(Wh + (size_t)r * (DFEAT / 2) + kc * (KCH / 2) + w4 * 4);
            if (NPASS >= 3)
                *(uint4*)(Bsl + r * STR + w4 * 4) =
                    *(const uint4*)(Wl + (size_t)r * (DFEAT / 2) + kc * (KCH / 2) + w4 * 4);
        }
        __syncthreads();

        #pragma unroll
        for (int kk2 = 0; kk2 < KCH / 2; kk2 += 8) {
            uint32_t kb = (uint32_t)(kk2 * 4);
            uint32_t ah[2][4], al[2][4];
            #pragma unroll
            for (int mt = 0; mt < 2; mt++) {
                LDSM_X4(ah[mt][0], ah[mt][1], ah[mt][2], ah[mt][3],
                        ash32 + aoffA[mt] + kb);
                LDSM_X4(al[mt][0], al[mt][1], al[mt][2], al[mt][3],
                        asl32 + aoffA[mt] + kb);
            }
            #pragma unroll
            for (int p = 0; p < WM; p++) {
                uint32_t pboff = aoffB + (uint32_t)(p * 16 * STR * 4);
                uint32_t bh0, bh1, bh2, bh3;
                LDSM_X4(bh0, bh1, bh2, bh3, bsh32 + pboff + kb);
                #pragma unroll
                for (int mt = 0; mt < 2; mt++) {
                    MMA_F16(acc[mt][2 * p],     ah[mt][0], ah[mt][1], ah[mt][2], ah[mt][3], bh0, bh1);
                    MMA_F16(acc[mt][2 * p],     al[mt][0], al[mt][1], al[mt][2], al[mt][3], bh0, bh1);
                    MMA_F16(acc[mt][2 * p + 1], ah[mt][0], ah[mt][1], ah[mt][2], ah[mt][3], bh2, bh3);
                    MMA_F16(acc[mt][2 * p + 1], al[mt][0], al[mt][1], al[mt][2], al[mt][3], bh2, bh3);
                }
                if (NPASS >= 3) {
                    uint32_t bl0, bl1, bl2, bl3;
                    LDSM_X4(bl0, bl1, bl2, bl3, bsl32 + pboff + kb);
                    #pragma unroll
                    for (int mt = 0; mt < 2; mt++) {
                        MMA_F16(acc[mt][2 * p],     ah[mt][0], ah[mt][1], ah[mt][2], ah[mt][3], bl0, bl1);
                        MMA_F16(acc[mt][2 * p + 1], ah[mt][0], ah[mt][1], ah[mt][2], ah[mt][3], bl2, bl3);
                    }
                }
            }
        }
        __syncthreads();
    }

    #pragma unroll
    for (int nt = 0; nt < NT; nt++) {
        int col = wn * (16 * WM) + nt * 8 + 2 * qi;
        float bx2 = bias[col], by = bias[col + 1];
        #pragma unroll
        for (int mt = 0; mt < 2; mt++) {
            int r0 = row0 + wm * 32 + mt * 16 + qp;
            float v0 = acc[mt][nt][0] + bx2;
            float v1 = acc[mt][nt][1] + by;
            float v2 = acc[mt][nt][2] + bx2;
            float v3 = acc[mt][nt][3] + by;
            if (do_relu) {
                v0 = fmaxf(v0, 0.f); v1 = fmaxf(v1, 0.f);
                v2 = fmaxf(v2, 0.f); v3 = fmaxf(v3, 0.f);
            }
            *(float2*)(C + (size_t)r0 * (2 * OUTD) + coloff + col)       = make_float2(v0, v1);
            *(float2*)(C + (size_t)(r0 + 8) * (2 * OUTD) + coloff + col) = make_float2(v2, v3);
        }
    }
}

// ---- fused launch 1: x-branch layer-1 GEMM (no mean dependency) + all means
// blocks [0,400): z1 x-tiles | [400,416): z0 x-tiles | [416,672): mean25 -> m1
// | [672,7072): mean10 -> m2.  GEMM tiles first (long); means fill the machine.
__global__ __launch_bounds__(256, 4)
void fused_x_means_kernel(const float* __restrict__ feats,
                          const int* __restrict__ ids,
                          const float* __restrict__ b1x) {
    extern __shared__ uint32_t smx[];
    int bx = blockIdx.x;
    if (bx < NBG_Z1) {
        gemm_tile<2, 2>(feats, d_ids1, d_Whh, d_Wll, b1x, d_z1,
                        bx * 64, 0, 1, smx);
    } else if (bx < NBG_Z1 + NBG_Z0) {
        gemm_tile<2, 2>(feats, ids, d_Whh, d_Wll, b1x, d_z0,
                        (bx - NBG_Z1) * 64, 0, 1, smx);
    } else if (bx < NBG_Z1 + NBG_Z0 + NB25) {
        mean_body<FAN1>(feats, d_ids1, d_m1, bx - NBG_Z1 - NBG_Z0);
    } else {
        mean_body<FAN2>(feats, d_ids2, d_m2, bx - NBG_Z1 - NBG_Z0 - NB25);
    }
}

// ---- launch 2: n-branch layer-1 GEMM (consumes m2/m1)
__global__ __launch_bounds__(256, 4)
void l1_n_kernel(const float* __restrict__ b1n) {
    extern __shared__ uint32_t smx[];
    int bx = blockIdx.x;
    if (bx < NBG_Z1)
        gemm_tile<2, 2>(d_m2, nullptr, d_Whh + WSZH, d_Wll + WSZH, b1n, d_z1,
                        bx * 64, OUTD, 1, smx);
    else
        gemm_tile<2, 2>(d_m1, nullptr, d_Whh + WSZH, d_Wll + WSZH, b1n, d_z0,
                        (bx - NBG_Z1) * 64, OUTD, 1, smx);
}

// ---- launch 4: output layer (both branches via gridDim.y, 3-pass, BM=32)
__global__ __launch_bounds__(256, 3)
void out_kernel(const float* __restrict__ b2x, const float* __restrict__ b2n,
                float* __restrict__ out) {
    extern __shared__ uint32_t smx[];
    int bx = blockIdx.x;
    if (blockIdx.y == 0)
        gemm_tile<1, 3>(d_z0, nullptr, d_Whh + 2 * WSZH, d_Wll + 2 * WSZH,
                        b2x, out, bx * 32, 0, 0, smx);
    else
        gemm_tile<1, 3>(d_m3, nullptr, d_Whh + 3 * WSZH, d_Wll + 3 * WSZH,
                        b2n, out, bx * 32, OUTD, 0, smx);
}

// ---------------- host launcher ----------------
extern "C" void kernel_launch(void* const* d_in, const int* in_sizes, int n_in,
                              void* d_out, int out_size) {
    const int*   ids   = (const int*)d_in[0];
    const int*   adj   = (const int*)d_in[1];
    const float* feats = (const float*)d_in[2];
    const float* W1x   = (const float*)d_in[3];
    const float* b1x   = (const float*)d_in[4];
    const float* W1n   = (const float*)d_in[5];
    const float* b1n   = (const float*)d_in[6];
    const float* W2x   = (const float*)d_in[7];
    const float* b2x   = (const float*)d_in[8];
    const float* W2n   = (const float*)d_in[9];
    const float* b2n   = (const float*)d_in[10];
    float* out = (float*)d_out;

    float* p_z1;
    cudaGetSymbolAddress((void**)&p_z1, d_z1);

    const int SMEM_L1  = (2 * 64 * STR + OUTD * STR) * 4;      // 36864 B (NPASS=2)
    const int SMEM_OUT = (2 * 32 * STR + 2 * OUTD * STR) * 4;  // 46080 B (NPASS=3)
    cudaFuncSetAttribute(fused_x_means_kernel,
                         cudaFuncAttributeMaxDynamicSharedMemorySize, SMEM_L1);
    cudaFuncSetAttribute(l1_n_kernel,
                         cudaFuncAttributeMaxDynamicSharedMemorySize, SMEM_L1);
    cudaFuncSetAttribute(out_kernel,
                         cudaFuncAttributeMaxDynamicSharedMemorySize, SMEM_OUT);

    // 1. permutations (threefry, partitionable, bits1 ^ bits2)
    setup_perm_kernel<<<1, 128>>>();
    // 2. weight fp16 hi/lo split
    split_w_kernel<<<dim3(WSZH / 256, 4), 256>>>(W1x, W1n, W2x, W2n);
    // 3. neighbor id tables
    build_ids_kernel<<<(M1 + 255) / 256, 256>>>(ids, adj);
    // 4. FUSED: x-branch layer-1 GEMM (z1/z0 cols [0,128)) + m1 + m2 means
    fused_x_means_kernel<<<NBG_Z1 + NBG_Z0 + NB25 + NB10, 256, SMEM_L1>>>(
        feats, ids, b1x);
    // 5. n-branch layer-1 GEMM (z1/z0 cols [128,256)), consumes m2/m1
    l1_n_kernel<<<NBG_Z1 + NBG_Z0, 256, SMEM_L1>>>(b1n);
    // 6. m3 = mean25(z1 contiguous groups)
    mean_m3_kernel<<<NB25, 256>>>(p_z1);
    // 7. out = [z0@W2x + b2x | m3@W2n + b2n]  (no relu)
    out_kernel<<<dim3(BATCH / 32, 2), 256, SMEM_OUT>>>(b2x, b2n, out);
}